// round 1
// baseline (speedup 1.0000x reference)
#include <cuda_runtime.h>
#include <cstdint>
#include <cstddef>

#define N_TOK 4096
#define DCH   256
#define NHEAD 4
#define DHEAD 64

// Scratch (static device arrays — no allocation at any time)
__device__ float g_Q  [DCH * N_TOK];
__device__ float g_K  [DCH * N_TOK];
__device__ float g_V  [DCH * N_TOK];
__device__ float g_msg[DCH * N_TOK];
__device__ float g_h1 [(DCH/2) * N_TOK];
__device__ float g_h2 [(DCH/2) * N_TOK];

typedef unsigned long long u64;

__device__ __forceinline__ u64 pack2(float lo, float hi) {
    u64 r; asm("mov.b64 %0, {%1,%2};" : "=l"(r) : "f"(lo), "f"(hi)); return r;
}
__device__ __forceinline__ void unpack2(u64 v, float& lo, float& hi) {
    asm("mov.b64 {%0,%1}, %2;" : "=f"(lo), "=f"(hi) : "l"(v));
}
// d += a * b  (packed f32x2)
__device__ __forceinline__ void fma2(u64& d, u64 a, u64 b) {
    asm("fma.rn.f32x2 %0, %1, %2, %0;" : "+l"(d) : "l"(a), "l"(b));
}
// d += a  (packed f32x2)
__device__ __forceinline__ void add2(u64& d, u64 a) {
    asm("add.rn.f32x2 %0, %0, %1;" : "+l"(d) : "l"(a));
}

// ---------------------------------------------------------------------------
// SIMT GEMM with packed f32x2 FMAs.
// C[M, 4096] = A[M,K] (row-major) x B[K,4096] (row-major), plus epilogue.
// Tile 64x64, 128 threads, per-thread microtile 8(M) x 4(N) as 4x4 M-pairs.
// EPI: 0 = +bias ; 1 = bias + BN(eval) + ReLU ; 2 = bias + residual add
// ---------------------------------------------------------------------------
template<int EPI>
__global__ void __launch_bounds__(128)
gemm_kernel(const float* __restrict__ A, const float* __restrict__ B,
            float* __restrict__ C, const float* __restrict__ bias,
            const float* __restrict__ gamma, const float* __restrict__ beta,
            const float* __restrict__ resid, int K)
{
    __shared__ float As[16][68];   // [k][m], m contiguous (padded rows)
    __shared__ float Bs[16][64];   // [k][n]
    const int m0 = blockIdx.y * 64;
    const int n0 = blockIdx.x * 64;
    const int tid = threadIdx.x;
    const int tm = tid >> 4;       // 0..7  -> rows tm*8 .. tm*8+7
    const int tn = tid & 15;       // 0..15 -> cols tn*4 .. tn*4+3

    u64 c2[4][4];
    #pragma unroll
    for (int i = 0; i < 4; i++)
        #pragma unroll
        for (int j = 0; j < 4; j++) c2[i][j] = 0ull;

    const int am = tid >> 2;            // 0..31 (+32 second pass)
    const int ac = (tid & 3) << 2;      // k-chunk 0..12
    const int br = tid >> 4;            // 0..7 (+8 second pass)
    const int bc = (tid & 15) << 2;     // n-chunk

    for (int k0 = 0; k0 < K; k0 += 16) {
        // prefetch to regs
        const float4 av0 = *(const float4*)(A + (size_t)(m0 + am     ) * K + k0 + ac);
        const float4 av1 = *(const float4*)(A + (size_t)(m0 + am + 32) * K + k0 + ac);
        const float4 bv0 = *(const float4*)(B + (size_t)(k0 + br    ) * N_TOK + n0 + bc);
        const float4 bv1 = *(const float4*)(B + (size_t)(k0 + br + 8) * N_TOK + n0 + bc);
        __syncthreads();
        As[ac+0][am]    = av0.x; As[ac+1][am]    = av0.y; As[ac+2][am]    = av0.z; As[ac+3][am]    = av0.w;
        As[ac+0][am+32] = av1.x; As[ac+1][am+32] = av1.y; As[ac+2][am+32] = av1.z; As[ac+3][am+32] = av1.w;
        *(float4*)&Bs[br  ][bc] = bv0;
        *(float4*)&Bs[br+8][bc] = bv1;
        __syncthreads();

        #pragma unroll
        for (int k = 0; k < 16; k++) {
            u64 a2[4];
            const float2* arow = (const float2*)&As[k][tm << 3];
            #pragma unroll
            for (int i = 0; i < 4; i++) { float2 t = arow[i]; a2[i] = pack2(t.x, t.y); }
            const float4 bv = *(const float4*)&Bs[k][tn << 2];
            u64 b2[4];
            b2[0] = pack2(bv.x, bv.x); b2[1] = pack2(bv.y, bv.y);
            b2[2] = pack2(bv.z, bv.z); b2[3] = pack2(bv.w, bv.w);
            #pragma unroll
            for (int i = 0; i < 4; i++)
                #pragma unroll
                for (int j = 0; j < 4; j++)
                    fma2(c2[i][j], a2[i], b2[j]);
        }
    }

    // epilogue: rows m0 + tm*8 + 2i + {0,1}, cols n0 + tn*4 .. +3
    #pragma unroll
    for (int i = 0; i < 4; i++) {
        float lo[4], hi[4];
        #pragma unroll
        for (int j = 0; j < 4; j++) unpack2(c2[i][j], lo[j], hi[j]);
        const int mlo = m0 + (tm << 3) + 2 * i;
        const int mhi = mlo + 1;
        const int nc  = n0 + (tn << 2);

        float* rows[2] = { lo, hi };
        int    ms[2]   = { mlo, mhi };
        #pragma unroll
        for (int r = 0; r < 2; r++) {
            float* v = rows[r];
            const int m = ms[r];
            const float b = bias[m];
            float4 o;
            if (EPI == 0) {
                o.x = v[0] + b; o.y = v[1] + b; o.z = v[2] + b; o.w = v[3] + b;
            } else if (EPI == 1) {
                const float s  = gamma[m] * rsqrtf(1.0f + 1e-5f);
                const float bb = beta[m];
                o.x = fmaxf((v[0] + b) * s + bb, 0.0f);
                o.y = fmaxf((v[1] + b) * s + bb, 0.0f);
                o.z = fmaxf((v[2] + b) * s + bb, 0.0f);
                o.w = fmaxf((v[3] + b) * s + bb, 0.0f);
            } else {
                const float4 rr = *(const float4*)(resid + (size_t)m * N_TOK + nc);
                o.x = v[0] + b + rr.x; o.y = v[1] + b + rr.y;
                o.z = v[2] + b + rr.z; o.w = v[3] + b + rr.w;
            }
            *(float4*)(C + (size_t)m * N_TOK + nc) = o;
        }
    }
}

// ---------------------------------------------------------------------------
// Fused attention: one thread = one (head, query). Single pass over all keys,
// shift-free softmax accumulation (logits provably bounded ~|4|), packed
// f32x2 FMAs for both Q.K and P.V. K/V tiles (64 keys) staged in smem and
// read broadcast (all lanes consume the same key -> conflict-free).
// grid = (4 heads, 32 query tiles), block = 128 threads.
// Head is the fast grid dim so the 4 heads of a query tile co-reside and
// share spatial rows through L2.
// ---------------------------------------------------------------------------
__global__ void __launch_bounds__(128)
attn_kernel(const float* __restrict__ spat)
{
    __shared__ float Ks[64 * 68];   // [key][dim], row stride 68 (16B aligned)
    __shared__ float Vs[64 * 68];
    const int h = blockIdx.x;
    const int q = blockIdx.y * 128 + threadIdx.x;
    const float SCL = 0.1803368801111204f;   // log2(e) / sqrt(DH) = log2(e)/8

    // Q row (64 dims), pre-scaled so p = exp2(s * spatial)
    u64 q2[32];
    #pragma unroll
    for (int j = 0; j < 32; j++) {
        const float a = g_Q[(size_t)(h * DHEAD + 2*j    ) * N_TOK + q] * SCL;
        const float b = g_Q[(size_t)(h * DHEAD + 2*j + 1) * N_TOK + q] * SCL;
        q2[j] = pack2(a, b);
    }
    u64 o2[32];
    #pragma unroll
    for (int j = 0; j < 32; j++) o2[j] = 0ull;
    float denom = 0.0f;

    const float* sprow = spat + (size_t)q * N_TOK;
    const int tds = threadIdx.x >> 4;          // dim slice 0..7 (+8 per pass)
    const int tks = (threadIdx.x & 15) << 2;   // key offset 0..60

    #pragma unroll 1
    for (int kb = 0; kb < N_TOK; kb += 64) {
        __syncthreads();
        #pragma unroll
        for (int pass = 0; pass < 8; ++pass) {
            const int dd = tds + pass * 8;
            const float4 kv = *(const float4*)(g_K + (size_t)(h * DHEAD + dd) * N_TOK + kb + tks);
            Ks[(tks+0)*68 + dd] = kv.x; Ks[(tks+1)*68 + dd] = kv.y;
            Ks[(tks+2)*68 + dd] = kv.z; Ks[(tks+3)*68 + dd] = kv.w;
            const float4 vv = *(const float4*)(g_V + (size_t)(h * DHEAD + dd) * N_TOK + kb + tks);
            Vs[(tks+0)*68 + dd] = vv.x; Vs[(tks+1)*68 + dd] = vv.y;
            Vs[(tks+2)*68 + dd] = vv.z; Vs[(tks+3)*68 + dd] = vv.w;
        }
        __syncthreads();

        #pragma unroll 1
        for (int g = 0; g < 16; ++g) {
            const float4 sp = *(const float4*)(sprow + kb + (g << 2));
            const float spv[4] = { sp.x, sp.y, sp.z, sp.w };
            #pragma unroll
            for (int kk = 0; kk < 4; ++kk) {
                const int k = (g << 2) + kk;
                const ulonglong2* krow = (const ulonglong2*)(Ks + k * 68);
                u64 acc[4];
                acc[0] = acc[1] = acc[2] = acc[3] = 0ull;
                #pragma unroll
                for (int j = 0; j < 16; j++) {
                    const ulonglong2 t = krow[j];
                    fma2(acc[(2*j    ) & 3], q2[2*j    ], t.x);
                    fma2(acc[(2*j + 1) & 3], q2[2*j + 1], t.y);
                }
                add2(acc[0], acc[1]); add2(acc[2], acc[3]); add2(acc[0], acc[2]);
                float lo, hi; unpack2(acc[0], lo, hi);
                const float p = exp2f((lo + hi) * spv[kk]);
                denom += p;
                const u64 p2 = pack2(p, p);
                const ulonglong2* vrow = (const ulonglong2*)(Vs + k * 68);
                #pragma unroll
                for (int j = 0; j < 16; j++) {
                    const ulonglong2 t = vrow[j];
                    fma2(o2[2*j    ], t.x, p2);
                    fma2(o2[2*j + 1], t.y, p2);
                }
            }
        }
    }

    const float inv = 1.0f / denom;
    #pragma unroll
    for (int j = 0; j < 32; j++) {
        float lo, hi; unpack2(o2[j], lo, hi);
        g_msg[(size_t)(h * DHEAD + 2*j    ) * N_TOK + q] = lo * inv;
        g_msg[(size_t)(h * DHEAD + 2*j + 1) * N_TOK + q] = hi * inv;
    }
}

// ---------------------------------------------------------------------------
extern "C" void kernel_launch(void* const* d_in, const int* in_sizes, int n_in,
                              void* d_out, int out_size)
{
    const float* x    = (const float*)d_in[0];
    const float* spat = (const float*)d_in[1];
    const float* Wq   = (const float*)d_in[2];
    const float* bq   = (const float*)d_in[3];
    const float* Wk   = (const float*)d_in[4];
    const float* bk   = (const float*)d_in[5];
    const float* Wv   = (const float*)d_in[6];
    const float* bv   = (const float*)d_in[7];
    const float* W1   = (const float*)d_in[8];
    const float* b1   = (const float*)d_in[9];
    const float* g1   = (const float*)d_in[10];
    const float* be1  = (const float*)d_in[11];
    const float* W2   = (const float*)d_in[12];
    const float* b2   = (const float*)d_in[13];
    const float* g2   = (const float*)d_in[14];
    const float* be2  = (const float*)d_in[15];
    const float* W3   = (const float*)d_in[16];
    const float* b3   = (const float*)d_in[17];
    float* out = (float*)d_out;

    float *pQ, *pK, *pV, *pM, *pH1, *pH2;
    cudaGetSymbolAddress((void**)&pQ,  g_Q);
    cudaGetSymbolAddress((void**)&pK,  g_K);
    cudaGetSymbolAddress((void**)&pV,  g_V);
    cudaGetSymbolAddress((void**)&pM,  g_msg);
    cudaGetSymbolAddress((void**)&pH1, g_h1);
    cudaGetSymbolAddress((void**)&pH2, g_h2);

    const dim3 blk(128);
    // QKV projections: [256,256] x [256,4096]
    gemm_kernel<0><<<dim3(64, 4), blk>>>(Wq, x, pQ, bq, nullptr, nullptr, nullptr, 256);
    gemm_kernel<0><<<dim3(64, 4), blk>>>(Wk, x, pK, bk, nullptr, nullptr, nullptr, 256);
    gemm_kernel<0><<<dim3(64, 4), blk>>>(Wv, x, pV, bv, nullptr, nullptr, nullptr, 256);
    // fused attention -> g_msg
    attn_kernel<<<dim3(4, 32), blk>>>(spat);
    // message MLP
    gemm_kernel<1><<<dim3(64, 2), blk>>>(W1, pM,  pH1, b1, g1, be1, nullptr, 256);
    gemm_kernel<1><<<dim3(64, 2), blk>>>(W2, pH1, pH2, b2, g2, be2, nullptr, 128);
    gemm_kernel<2><<<dim3(64, 4), blk>>>(W3, pH2, out, b3, nullptr, nullptr, x, 128);
}

// round 5
// speedup vs baseline: 6.2524x; 6.2524x over previous
#include <cuda_runtime.h>
#include <cuda_fp16.h>
#include <cstdint>
#include <cstddef>

#define N_TOK 4096
#define DCH   256
#define NHEAD 4
#define DHEAD 64

// Scratch (static device arrays — no allocation anywhere)
__device__ __half g_Qh[NHEAD * N_TOK * DHEAD];  // [h][tok][d]
__device__ __half g_Kh[NHEAD * N_TOK * DHEAD];  // [h][tok][d]
__device__ __half g_Vh[DCH * N_TOK];            // [ch][tok]
__device__ float  g_msg[DCH * N_TOK];
__device__ float  g_h1 [(DCH/2) * N_TOK];
__device__ float  g_h2 [(DCH/2) * N_TOK];

typedef unsigned long long u64;

__device__ __forceinline__ u64 pack2(float lo, float hi) {
    u64 r; asm("mov.b64 %0, {%1,%2};" : "=l"(r) : "f"(lo), "f"(hi)); return r;
}
__device__ __forceinline__ void unpack2(u64 v, float& lo, float& hi) {
    asm("mov.b64 {%0,%1}, %2;" : "=f"(lo), "=f"(hi) : "l"(v));
}
__device__ __forceinline__ void fma2(u64& d, u64 a, u64 b) {
    asm("fma.rn.f32x2 %0, %1, %2, %0;" : "+l"(d) : "l"(a), "l"(b));
}
__device__ __forceinline__ float ex2f(float x) {
    float r; asm("ex2.approx.f32 %0, %1;" : "=f"(r) : "f"(x)); return r;
}
// HMMA m16n8k16 f16 -> f32 accum (sm_80+ baseline ISA, works on sm_100)
__device__ __forceinline__ void hmma(float* c, const uint32_t* a, const uint32_t* b) {
    asm volatile(
        "mma.sync.aligned.m16n8k16.row.col.f32.f16.f16.f32 "
        "{%0,%1,%2,%3}, {%4,%5,%6,%7}, {%8,%9}, {%0,%1,%2,%3};"
        : "+f"(c[0]), "+f"(c[1]), "+f"(c[2]), "+f"(c[3])
        : "r"(a[0]), "r"(a[1]), "r"(a[2]), "r"(a[3]), "r"(b[0]), "r"(b[1]));
}

// ---------------------------------------------------------------------------
// SIMT GEMM with packed f32x2 FMAs.  C[M,4096] = A[M,K] x B[K,4096]
// EPI 0: bias, f16 token-major [h][tok][d]   (Q, K)
// EPI 3: bias, f16 channel-major [ch][tok]   (V)
// EPI 1: bias + BN + ReLU, f32               (MLP hidden)
// EPI 2: bias + residual, f32                (output)
// ---------------------------------------------------------------------------
template<int EPI>
__global__ void __launch_bounds__(128)
gemm_kernel(const float* __restrict__ A, const float* __restrict__ B,
            void* __restrict__ Cv, const float* __restrict__ bias,
            const float* __restrict__ gamma, const float* __restrict__ beta,
            const float* __restrict__ resid, int K)
{
    __shared__ float As[16][68];
    __shared__ float Bs[16][64];
    const int m0 = blockIdx.y * 64;
    const int n0 = blockIdx.x * 64;
    const int tid = threadIdx.x;
    const int tm = tid >> 4;
    const int tn = tid & 15;

    u64 c2[4][4];
    #pragma unroll
    for (int i = 0; i < 4; i++)
        #pragma unroll
        for (int j = 0; j < 4; j++) c2[i][j] = 0ull;

    const int am = tid >> 2;
    const int ac = (tid & 3) << 2;
    const int br = tid >> 4;
    const int bc = (tid & 15) << 2;

    for (int k0 = 0; k0 < K; k0 += 16) {
        const float4 av0 = *(const float4*)(A + (size_t)(m0 + am     ) * K + k0 + ac);
        const float4 av1 = *(const float4*)(A + (size_t)(m0 + am + 32) * K + k0 + ac);
        const float4 bv0 = *(const float4*)(B + (size_t)(k0 + br    ) * N_TOK + n0 + bc);
        const float4 bv1 = *(const float4*)(B + (size_t)(k0 + br + 8) * N_TOK + n0 + bc);
        __syncthreads();
        As[ac+0][am]    = av0.x; As[ac+1][am]    = av0.y; As[ac+2][am]    = av0.z; As[ac+3][am]    = av0.w;
        As[ac+0][am+32] = av1.x; As[ac+1][am+32] = av1.y; As[ac+2][am+32] = av1.z; As[ac+3][am+32] = av1.w;
        *(float4*)&Bs[br  ][bc] = bv0;
        *(float4*)&Bs[br+8][bc] = bv1;
        __syncthreads();

        #pragma unroll
        for (int k = 0; k < 16; k++) {
            u64 a2[4];
            const float2* arow = (const float2*)&As[k][tm << 3];
            #pragma unroll
            for (int i = 0; i < 4; i++) { float2 t = arow[i]; a2[i] = pack2(t.x, t.y); }
            const float4 bv = *(const float4*)&Bs[k][tn << 2];
            u64 b2[4];
            b2[0] = pack2(bv.x, bv.x); b2[1] = pack2(bv.y, bv.y);
            b2[2] = pack2(bv.z, bv.z); b2[3] = pack2(bv.w, bv.w);
            #pragma unroll
            for (int i = 0; i < 4; i++)
                #pragma unroll
                for (int j = 0; j < 4; j++)
                    fma2(c2[i][j], a2[i], b2[j]);
        }
    }

    #pragma unroll
    for (int i = 0; i < 4; i++) {
        float lo[4], hi[4];
        #pragma unroll
        for (int j = 0; j < 4; j++) unpack2(c2[i][j], lo[j], hi[j]);
        const int mlo = m0 + (tm << 3) + 2 * i;
        const int mhi = mlo + 1;
        const int nc  = n0 + (tn << 2);

        if (EPI == 0) {
            __half* qh = (__half*)Cv;
            const int hh = mlo >> 6, d0 = mlo & 63;
            const float blo = bias[mlo], bhi = bias[mhi];
            #pragma unroll
            for (int j = 0; j < 4; j++) {
                __half2 v = __floats2half2_rn(lo[j] + blo, hi[j] + bhi);
                *(__half2*)(qh + ((size_t)hh * N_TOK + (nc + j)) * DHEAD + d0) = v;
            }
        } else if (EPI == 3) {
            __half* vh = (__half*)Cv;
            const float bl = bias[mlo], bh = bias[mhi];
            __half2 p0 = __floats2half2_rn(lo[0] + bl, lo[1] + bl);
            __half2 p1 = __floats2half2_rn(lo[2] + bl, lo[3] + bl);
            __half2 p2 = __floats2half2_rn(hi[0] + bh, hi[1] + bh);
            __half2 p3 = __floats2half2_rn(hi[2] + bh, hi[3] + bh);
            *(__half2*)(vh + (size_t)mlo * N_TOK + nc)     = p0;
            *(__half2*)(vh + (size_t)mlo * N_TOK + nc + 2) = p1;
            *(__half2*)(vh + (size_t)mhi * N_TOK + nc)     = p2;
            *(__half2*)(vh + (size_t)mhi * N_TOK + nc + 2) = p3;
        } else {
            float* C = (float*)Cv;
            float* rows[2] = { lo, hi };
            int    ms[2]   = { mlo, mhi };
            #pragma unroll
            for (int r = 0; r < 2; r++) {
                float* v = rows[r];
                const int m = ms[r];
                const float b = bias[m];
                float4 o;
                if (EPI == 1) {
                    const float s  = gamma[m] * rsqrtf(1.0f + 1e-5f);
                    const float bb = beta[m];
                    o.x = fmaxf((v[0] + b) * s + bb, 0.0f);
                    o.y = fmaxf((v[1] + b) * s + bb, 0.0f);
                    o.z = fmaxf((v[2] + b) * s + bb, 0.0f);
                    o.w = fmaxf((v[3] + b) * s + bb, 0.0f);
                } else {
                    const float4 rr = *(const float4*)(resid + (size_t)m * N_TOK + nc);
                    o.x = v[0] + b + rr.x; o.y = v[1] + b + rr.y;
                    o.z = v[2] + b + rr.z; o.w = v[3] + b + rr.w;
                }
                *(float4*)(C + (size_t)m * N_TOK + nc) = o;
            }
        }
    }
}

// ---------------------------------------------------------------------------
// Flash attention on HMMA (mma.sync m16n8k16). One CTA = (head, 128 queries),
// 8 warps x 16 queries. K/V staged per 128-key tile into smem in exact
// B-fragment order (LDS.64, conflict-free). S-accum fragments are reused
// in-register as A-fragments of P for the PV MMA. Shift-free softmax.
// Output transpose buffer row stride 66 (even) so float2 stores stay aligned.
// ---------------------------------------------------------------------------
__global__ void __launch_bounds__(256, 1)
attn_kernel(const float* __restrict__ spat)
{
    __shared__ __align__(16) char smbuf[33792];
    uint32_t* KF = (uint32_t*)smbuf;          // [kc(4)][nt(16)][lane(32)][r(2)] b32
    uint32_t* VF = KF + 4096;                 // [kc(8)][nt(8)][lane(32)][r(2)]  b32
    float*    SO = (float*)smbuf;             // out transpose: [q(128)][66]

    const int tid  = threadIdx.x;
    const int w    = tid >> 5;
    const int lane = tid & 31;
    const int h    = blockIdx.x;
    const int q0   = blockIdx.y * 128;
    const int g    = lane >> 2;        // row group 0..7
    const int tq   = lane & 3;         // col pair index
    const float SCL = 0.1803368801111204f;   // log2(e)/8

    // ---- Q fragments (persistent, from gmem) ----
    uint32_t aq[4][4];
    {
        const __half* qp = g_Qh + ((size_t)h * N_TOK + q0 + w * 16) * DHEAD;
        #pragma unroll
        for (int kc = 0; kc < 4; kc++) {
            const int d0 = kc * 16 + tq * 2;
            aq[kc][0] = *(const uint32_t*)(qp + (size_t)(g    ) * DHEAD + d0);
            aq[kc][1] = *(const uint32_t*)(qp + (size_t)(g + 8) * DHEAD + d0);
            aq[kc][2] = *(const uint32_t*)(qp + (size_t)(g    ) * DHEAD + d0 + 8);
            aq[kc][3] = *(const uint32_t*)(qp + (size_t)(g + 8) * DHEAD + d0 + 8);
        }
    }

    float oacc[8][4];
    #pragma unroll
    for (int i = 0; i < 8; i++)
        #pragma unroll
        for (int j = 0; j < 4; j++) oacc[i][j] = 0.0f;
    float denL = 0.0f, denH = 0.0f;

    const float* spL = spat + (size_t)(q0 + w * 16 + g    ) * N_TOK + tq * 2;
    const float* spH = spat + (size_t)(q0 + w * 16 + g + 8) * N_TOK + tq * 2;

    for (int t = 0; t < 32; t++) {
        const int kb = t * 128;
        __syncthreads();   // previous tile's fragment reads complete

        // ---- stage K into B-fragment order ----
        #pragma unroll
        for (int it = 0; it < 4; it++) {
            const int u = it * 256 + tid;
            const int tok = u >> 3, c8 = u & 7;
            const uint4 v = *(const uint4*)(g_Kh + ((size_t)h * N_TOK + kb + tok) * DHEAD + c8 * 8);
            const int kc = c8 >> 1, r = c8 & 1, nt = tok >> 3;
            uint32_t* p = KF + ((kc * 16 + nt) * 32 + (tok & 7) * 4) * 2 + r;
            p[0] = v.x; p[2] = v.y; p[4] = v.z; p[6] = v.w;
        }
        // ---- stage V into B-fragment order ----
        #pragma unroll
        for (int it = 0; it < 4; it++) {
            const int u = it * 256 + tid;
            const int d = u >> 4, c8 = u & 15;
            const int tok0 = c8 * 8;
            const uint4 v = *(const uint4*)(g_Vh + ((size_t)(h * DHEAD + d)) * N_TOK + kb + tok0);
            const int kc = tok0 >> 4, r = (tok0 >> 3) & 1, nt = d >> 3;
            uint32_t* p = VF + ((kc * 8 + nt) * 32 + (d & 7) * 4) * 2 + r;
            p[0] = v.x; p[2] = v.y; p[4] = v.z; p[6] = v.w;
        }
        __syncthreads();

        // ---- S = Q.K^T : 16 n-tiles of 8 keys, fp32 accum ----
        float cS[16][4];
        #pragma unroll
        for (int nt = 0; nt < 16; nt++)
            #pragma unroll
            for (int j = 0; j < 4; j++) cS[nt][j] = 0.0f;
        #pragma unroll
        for (int kc = 0; kc < 4; kc++)
            #pragma unroll
            for (int nt = 0; nt < 16; nt++)
                hmma(cS[nt], aq[kc], KF + ((kc * 16 + nt) * 32 + lane) * 2);

        // ---- softmax (shift-free) + repack P into A-fragments ----
        uint32_t aP[8][4];
        #pragma unroll
        for (int nt = 0; nt < 16; nt++) {
            const float2 slo = *(const float2*)(spL + kb + nt * 8);
            const float2 shi = *(const float2*)(spH + kb + nt * 8);
            const float p0 = ex2f(cS[nt][0] * slo.x * SCL);
            const float p1 = ex2f(cS[nt][1] * slo.y * SCL);
            const float p2 = ex2f(cS[nt][2] * shi.x * SCL);
            const float p3 = ex2f(cS[nt][3] * shi.y * SCL);
            denL += p0 + p1;
            denH += p2 + p3;
            __half2 h01 = __floats2half2_rn(p0, p1);
            __half2 h23 = __floats2half2_rn(p2, p3);
            aP[nt >> 1][(nt & 1) * 2 + 0] = *(uint32_t*)&h01;
            aP[nt >> 1][(nt & 1) * 2 + 1] = *(uint32_t*)&h23;
        }

        // ---- O += P.V ----
        #pragma unroll
        for (int kc = 0; kc < 8; kc++)
            #pragma unroll
            for (int nt = 0; nt < 8; nt++)
                hmma(oacc[nt], aP[kc], VF + ((kc * 8 + nt) * 32 + lane) * 2);
    }

    // quad reduce denominators (lanes in a quad share rows)
    denL += __shfl_xor_sync(0xFFFFFFFFu, denL, 1);
    denL += __shfl_xor_sync(0xFFFFFFFFu, denL, 2);
    denH += __shfl_xor_sync(0xFFFFFFFFu, denH, 1);
    denH += __shfl_xor_sync(0xFFFFFFFFu, denH, 2);
    const float invL = 1.0f / denL;
    const float invH = 1.0f / denH;

    __syncthreads();   // done with fragment smem; reuse as SO
    {
        const int rowL = w * 16 + g, rowH = rowL + 8;
        #pragma unroll
        for (int nt = 0; nt < 8; nt++) {
            const int col = nt * 8 + tq * 2;
            *(float2*)(SO + rowL * 66 + col) = make_float2(oacc[nt][0] * invL, oacc[nt][1] * invL);
            *(float2*)(SO + rowH * 66 + col) = make_float2(oacc[nt][2] * invH, oacc[nt][3] * invH);
        }
    }
    __syncthreads();

    // transposed, coalesced store: g_msg[(h*64+d)][q0..q0+127]
    #pragma unroll
    for (int it = 0; it < 8; it++) {
        const int u = it * 256 + tid;
        const int qc = u & 31, d = u >> 5;
        float4 o;
        o.x = SO[(qc * 4 + 0) * 66 + d];
        o.y = SO[(qc * 4 + 1) * 66 + d];
        o.z = SO[(qc * 4 + 2) * 66 + d];
        o.w = SO[(qc * 4 + 3) * 66 + d];
        *(float4*)(g_msg + (size_t)(h * DHEAD + d) * N_TOK + q0 + qc * 4) = o;
    }
}

// ---------------------------------------------------------------------------
extern "C" void kernel_launch(void* const* d_in, const int* in_sizes, int n_in,
                              void* d_out, int out_size)
{
    const float* x    = (const float*)d_in[0];
    const float* spat = (const float*)d_in[1];
    const float* Wq   = (const float*)d_in[2];
    const float* bq   = (const float*)d_in[3];
    const float* Wk   = (const float*)d_in[4];
    const float* bk   = (const float*)d_in[5];
    const float* Wv   = (const float*)d_in[6];
    const float* bv   = (const float*)d_in[7];
    const float* W1   = (const float*)d_in[8];
    const float* b1   = (const float*)d_in[9];
    const float* g1   = (const float*)d_in[10];
    const float* be1  = (const float*)d_in[11];
    const float* W2   = (const float*)d_in[12];
    const float* b2   = (const float*)d_in[13];
    const float* g2   = (const float*)d_in[14];
    const float* be2  = (const float*)d_in[15];
    const float* W3   = (const float*)d_in[16];
    const float* b3   = (const float*)d_in[17];
    float* out = (float*)d_out;

    void *pQh, *pKh, *pVh, *pM, *pH1, *pH2;
    cudaGetSymbolAddress(&pQh, g_Qh);
    cudaGetSymbolAddress(&pKh, g_Kh);
    cudaGetSymbolAddress(&pVh, g_Vh);
    cudaGetSymbolAddress(&pM,  g_msg);
    cudaGetSymbolAddress(&pH1, g_h1);
    cudaGetSymbolAddress(&pH2, g_h2);

    const dim3 blk(128);
    gemm_kernel<0><<<dim3(64, 4), blk>>>(Wq, x, pQh, bq, nullptr, nullptr, nullptr, 256);
    gemm_kernel<0><<<dim3(64, 4), blk>>>(Wk, x, pKh, bk, nullptr, nullptr, nullptr, 256);
    gemm_kernel<3><<<dim3(64, 4), blk>>>(Wv, x, pVh, bv, nullptr, nullptr, nullptr, 256);
    attn_kernel<<<dim3(4, 32), 256>>>(spat);
    gemm_kernel<1><<<dim3(64, 2), blk>>>(W1, (const float*)pM,  pH1, b1, g1, be1, nullptr, 256);
    gemm_kernel<1><<<dim3(64, 2), blk>>>(W2, (const float*)pH1, pH2, b2, g2, be2, nullptr, 128);
    gemm_kernel<2><<<dim3(64, 4), blk>>>(W3, (const float*)pH2, out, b3, nullptr, nullptr, x, 128);
}

// round 7
// speedup vs baseline: 6.2818x; 1.0047x over previous
#include <cuda_runtime.h>
#include <cuda_fp16.h>
#include <cstdint>
#include <cstddef>

#define N_TOK 4096
#define DCH   256
#define NHEAD 4
#define DHEAD 64
#define KSPLIT 2

// Scratch (static device arrays — no allocation anywhere)
__device__ __half g_Qh[NHEAD * N_TOK * DHEAD];  // [h][tok][d]
__device__ __half g_Kh[NHEAD * N_TOK * DHEAD];  // [h][tok][d]
__device__ __half g_Vh[DCH * N_TOK];            // [ch][tok]
__device__ float  g_msg[DCH * N_TOK];
__device__ float  g_pO [KSPLIT * DCH * N_TOK];  // split-K partial O, [kt][h*64+d][tok]
__device__ float  g_pden[KSPLIT * NHEAD * N_TOK];
__device__ float  g_h1 [(DCH/2) * N_TOK];
__device__ float  g_h2 [(DCH/2) * N_TOK];

typedef unsigned long long u64;

__device__ __forceinline__ u64 pack2(float lo, float hi) {
    u64 r; asm("mov.b64 %0, {%1,%2};" : "=l"(r) : "f"(lo), "f"(hi)); return r;
}
__device__ __forceinline__ void unpack2(u64 v, float& lo, float& hi) {
    asm("mov.b64 {%0,%1}, %2;" : "=f"(lo), "=f"(hi) : "l"(v));
}
__device__ __forceinline__ void fma2(u64& d, u64 a, u64 b) {
    asm("fma.rn.f32x2 %0, %1, %2, %0;" : "+l"(d) : "l"(a), "l"(b));
}
__device__ __forceinline__ float ex2f(float x) {
    float r; asm("ex2.approx.f32 %0, %1;" : "=f"(r) : "f"(x)); return r;
}
// HMMA m16n8k16 f16 -> f32 accum
__device__ __forceinline__ void hmma(float* c, const uint32_t* a, const uint32_t* b) {
    asm volatile(
        "mma.sync.aligned.m16n8k16.row.col.f32.f16.f16.f32 "
        "{%0,%1,%2,%3}, {%4,%5,%6,%7}, {%8,%9}, {%0,%1,%2,%3};"
        : "+f"(c[0]), "+f"(c[1]), "+f"(c[2]), "+f"(c[3])
        : "r"(a[0]), "r"(a[1]), "r"(a[2]), "r"(a[3]), "r"(b[0]), "r"(b[1]));
}

// ---------------------------------------------------------------------------
// SIMT GEMM with packed f32x2 FMAs (unchanged from passing round).
// ---------------------------------------------------------------------------
template<int EPI>
__global__ void __launch_bounds__(128)
gemm_kernel(const float* __restrict__ A, const float* __restrict__ B,
            void* __restrict__ Cv, const float* __restrict__ bias,
            const float* __restrict__ gamma, const float* __restrict__ beta,
            const float* __restrict__ resid, int K)
{
    __shared__ float As[16][68];
    __shared__ float Bs[16][64];
    const int m0 = blockIdx.y * 64;
    const int n0 = blockIdx.x * 64;
    const int tid = threadIdx.x;
    const int tm = tid >> 4;
    const int tn = tid & 15;

    u64 c2[4][4];
    #pragma unroll
    for (int i = 0; i < 4; i++)
        #pragma unroll
        for (int j = 0; j < 4; j++) c2[i][j] = 0ull;

    const int am = tid >> 2;
    const int ac = (tid & 3) << 2;
    const int br = tid >> 4;
    const int bc = (tid & 15) << 2;

    for (int k0 = 0; k0 < K; k0 += 16) {
        const float4 av0 = *(const float4*)(A + (size_t)(m0 + am     ) * K + k0 + ac);
        const float4 av1 = *(const float4*)(A + (size_t)(m0 + am + 32) * K + k0 + ac);
        const float4 bv0 = *(const float4*)(B + (size_t)(k0 + br    ) * N_TOK + n0 + bc);
        const float4 bv1 = *(const float4*)(B + (size_t)(k0 + br + 8) * N_TOK + n0 + bc);
        __syncthreads();
        As[ac+0][am]    = av0.x; As[ac+1][am]    = av0.y; As[ac+2][am]    = av0.z; As[ac+3][am]    = av0.w;
        As[ac+0][am+32] = av1.x; As[ac+1][am+32] = av1.y; As[ac+2][am+32] = av1.z; As[ac+3][am+32] = av1.w;
        *(float4*)&Bs[br  ][bc] = bv0;
        *(float4*)&Bs[br+8][bc] = bv1;
        __syncthreads();

        #pragma unroll
        for (int k = 0; k < 16; k++) {
            u64 a2[4];
            const float2* arow = (const float2*)&As[k][tm << 3];
            #pragma unroll
            for (int i = 0; i < 4; i++) { float2 t = arow[i]; a2[i] = pack2(t.x, t.y); }
            const float4 bv = *(const float4*)&Bs[k][tn << 2];
            u64 b2[4];
            b2[0] = pack2(bv.x, bv.x); b2[1] = pack2(bv.y, bv.y);
            b2[2] = pack2(bv.z, bv.z); b2[3] = pack2(bv.w, bv.w);
            #pragma unroll
            for (int i = 0; i < 4; i++)
                #pragma unroll
                for (int j = 0; j < 4; j++)
                    fma2(c2[i][j], a2[i], b2[j]);
        }
    }

    #pragma unroll
    for (int i = 0; i < 4; i++) {
        float lo[4], hi[4];
        #pragma unroll
        for (int j = 0; j < 4; j++) unpack2(c2[i][j], lo[j], hi[j]);
        const int mlo = m0 + (tm << 3) + 2 * i;
        const int mhi = mlo + 1;
        const int nc  = n0 + (tn << 2);

        if (EPI == 0) {
            __half* qh = (__half*)Cv;
            const int hh = mlo >> 6, d0 = mlo & 63;
            const float blo = bias[mlo], bhi = bias[mhi];
            #pragma unroll
            for (int j = 0; j < 4; j++) {
                __half2 v = __floats2half2_rn(lo[j] + blo, hi[j] + bhi);
                *(__half2*)(qh + ((size_t)hh * N_TOK + (nc + j)) * DHEAD + d0) = v;
            }
        } else if (EPI == 3) {
            __half* vh = (__half*)Cv;
            const float bl = bias[mlo], bh = bias[mhi];
            __half2 p0 = __floats2half2_rn(lo[0] + bl, lo[1] + bl);
            __half2 p1 = __floats2half2_rn(lo[2] + bl, lo[3] + bl);
            __half2 p2 = __floats2half2_rn(hi[0] + bh, hi[1] + bh);
            __half2 p3 = __floats2half2_rn(hi[2] + bh, hi[3] + bh);
            *(__half2*)(vh + (size_t)mlo * N_TOK + nc)     = p0;
            *(__half2*)(vh + (size_t)mlo * N_TOK + nc + 2) = p1;
            *(__half2*)(vh + (size_t)mhi * N_TOK + nc)     = p2;
            *(__half2*)(vh + (size_t)mhi * N_TOK + nc + 2) = p3;
        } else {
            float* C = (float*)Cv;
            float* rows[2] = { lo, hi };
            int    ms[2]   = { mlo, mhi };
            #pragma unroll
            for (int r = 0; r < 2; r++) {
                float* v = rows[r];
                const int m = ms[r];
                const float b = bias[m];
                float4 o;
                if (EPI == 1) {
                    const float s  = gamma[m] * rsqrtf(1.0f + 1e-5f);
                    const float bb = beta[m];
                    o.x = fmaxf((v[0] + b) * s + bb, 0.0f);
                    o.y = fmaxf((v[1] + b) * s + bb, 0.0f);
                    o.z = fmaxf((v[2] + b) * s + bb, 0.0f);
                    o.w = fmaxf((v[3] + b) * s + bb, 0.0f);
                } else {
                    const float4 rr = *(const float4*)(resid + (size_t)m * N_TOK + nc);
                    o.x = v[0] + b + rr.x; o.y = v[1] + b + rr.y;
                    o.z = v[2] + b + rr.z; o.w = v[3] + b + rr.w;
                }
                *(float4*)(C + (size_t)m * N_TOK + nc) = o;
            }
        }
    }
}

// ---------------------------------------------------------------------------
// Flash attention on HMMA, split-K (2-way), 2 CTAs/SM.
// CTA = (head, 128-query tile, key half). 8 warps x 16 queries, 16 key tiles.
// Fragment staging uses +kc*2 b32 skew -> conflict-free STS; reads stay
// contiguous-256B LDS.64 (8B-aligned). Inner loop chunked per 16 keys so the
// S accumulator is only 8 regs (fits 2 CTAs/SM).  Partials (unnormalized O,
// denom) written to g_pO/g_pden; combine kernel finishes the softmax divide.
// ---------------------------------------------------------------------------
__global__ void __launch_bounds__(256, 2)
attn_kernel(const float* __restrict__ spat)
{
    __shared__ __align__(16) char smbuf[33792];
    uint32_t* KF = (uint32_t*)smbuf;            // skewed frags, 16404B
    uint32_t* VF = (uint32_t*)(smbuf + 16448);  // skewed frags, 16436B
    float*    SO = (float*)smbuf;               // out transpose [128][66]

    const int tid  = threadIdx.x;
    const int w    = tid >> 5;
    const int lane = tid & 31;
    const int h    = blockIdx.x;
    const int q0   = blockIdx.y * 128;
    const int kt   = blockIdx.z;
    const int g    = lane >> 2;
    const int tq   = lane & 3;
    const float SCL = 0.1803368801111204f;   // log2(e)/8

    // ---- persistent Q fragments ----
    uint32_t aq[4][4];
    {
        const __half* qp = g_Qh + ((size_t)h * N_TOK + q0 + w * 16) * DHEAD;
        #pragma unroll
        for (int kc = 0; kc < 4; kc++) {
            const int d0 = kc * 16 + tq * 2;
            aq[kc][0] = *(const uint32_t*)(qp + (size_t)(g    ) * DHEAD + d0);
            aq[kc][1] = *(const uint32_t*)(qp + (size_t)(g + 8) * DHEAD + d0);
            aq[kc][2] = *(const uint32_t*)(qp + (size_t)(g    ) * DHEAD + d0 + 8);
            aq[kc][3] = *(const uint32_t*)(qp + (size_t)(g + 8) * DHEAD + d0 + 8);
        }
    }

    float oacc[8][4];
    #pragma unroll
    for (int i = 0; i < 8; i++)
        #pragma unroll
        for (int j = 0; j < 4; j++) oacc[i][j] = 0.0f;
    float denL = 0.0f, denH = 0.0f;

    const float* spL = spat + (size_t)(q0 + w * 16 + g    ) * N_TOK + tq * 2;
    const float* spH = spat + (size_t)(q0 + w * 16 + g + 8) * N_TOK + tq * 2;

    #pragma unroll 1
    for (int t = 0; t < 32 / KSPLIT; t++) {
        const int kb = (kt * (32 / KSPLIT) + t) * 128;
        __syncthreads();

        // ---- stage K frags (skew kc*2 -> banks = (tok&7)*8 + kc*2 + r, all distinct) ----
        #pragma unroll
        for (int it = 0; it < 4; it++) {
            const int u = it * 256 + tid;
            const int tok = u >> 3, c8 = u & 7;
            const uint4 v = *(const uint4*)(g_Kh + ((size_t)h * N_TOK + kb + tok) * DHEAD + c8 * 8);
            const int kc = c8 >> 1, r = c8 & 1, nt = tok >> 3;
            uint32_t* p = KF + (kc * 16 + nt) * 64 + kc * 2 + (tok & 7) * 8 + r;
            p[0] = v.x; p[2] = v.y; p[4] = v.z; p[6] = v.w;
        }
        // ---- stage V frags (d = tid>>2 spreads rows; banks = (d&7)*8 + kc*2 + r) ----
        #pragma unroll
        for (int it = 0; it < 4; it++) {
            const int d  = tid >> 2;
            const int c8 = it * 4 + (tid & 3);
            const uint4 v = *(const uint4*)(g_Vh + ((size_t)(h * DHEAD + d)) * N_TOK + kb + c8 * 8);
            const int kc = c8 >> 1, r = c8 & 1, nt = d >> 3;
            uint32_t* p = VF + (kc * 8 + nt) * 64 + kc * 2 + (d & 7) * 8 + r;
            p[0] = v.x; p[2] = v.y; p[4] = v.z; p[6] = v.w;
        }
        __syncthreads();

        // ---- 8 chunks of 16 keys: QK -> exp -> PV ----
        #pragma unroll
        for (int c = 0; c < 8; c++) {
            float cS[2][4];
            #pragma unroll
            for (int j = 0; j < 2; j++)
                #pragma unroll
                for (int q = 0; q < 4; q++) cS[j][q] = 0.0f;
            #pragma unroll
            for (int kc = 0; kc < 4; kc++) {
                hmma(cS[0], aq[kc], KF + (kc * 16 + 2 * c    ) * 64 + kc * 2 + lane * 2);
                hmma(cS[1], aq[kc], KF + (kc * 16 + 2 * c + 1) * 64 + kc * 2 + lane * 2);
            }
            uint32_t aP[4];
            #pragma unroll
            for (int j = 0; j < 2; j++) {
                const int nt = 2 * c + j;
                const float2 slo = *(const float2*)(spL + kb + nt * 8);
                const float2 shi = *(const float2*)(spH + kb + nt * 8);
                const float p0 = ex2f(cS[j][0] * slo.x * SCL);
                const float p1 = ex2f(cS[j][1] * slo.y * SCL);
                const float p2 = ex2f(cS[j][2] * shi.x * SCL);
                const float p3 = ex2f(cS[j][3] * shi.y * SCL);
                denL += p0 + p1;
                denH += p2 + p3;
                __half2 h01 = __floats2half2_rn(p0, p1);
                __half2 h23 = __floats2half2_rn(p2, p3);
                aP[j * 2 + 0] = *(uint32_t*)&h01;
                aP[j * 2 + 1] = *(uint32_t*)&h23;
            }
            #pragma unroll
            for (int ntv = 0; ntv < 8; ntv++)
                hmma(oacc[ntv], aP, VF + (c * 8 + ntv) * 64 + c * 2 + lane * 2);
        }
    }

    // quad-reduce denominators
    denL += __shfl_xor_sync(0xFFFFFFFFu, denL, 1);
    denL += __shfl_xor_sync(0xFFFFFFFFu, denL, 2);
    denH += __shfl_xor_sync(0xFFFFFFFFu, denH, 1);
    denH += __shfl_xor_sync(0xFFFFFFFFu, denH, 2);
    if (tq == 0) {
        float* dp = g_pden + (size_t)kt * NHEAD * N_TOK + (size_t)h * N_TOK + q0 + w * 16;
        dp[g]     = denL;
        dp[g + 8] = denH;
    }

    __syncthreads();   // fragment smem -> SO reuse
    {
        const int rowL = w * 16 + g, rowH = rowL + 8;
        #pragma unroll
        for (int nt = 0; nt < 8; nt++) {
            const int col = nt * 8 + tq * 2;
            *(float2*)(SO + rowL * 66 + col) = make_float2(oacc[nt][0], oacc[nt][1]);
            *(float2*)(SO + rowH * 66 + col) = make_float2(oacc[nt][2], oacc[nt][3]);
        }
    }
    __syncthreads();

    // transposed coalesced partial store: g_pO[kt][(h*64+d)][q0..q0+127]
    float* pO = g_pO + (size_t)kt * DCH * N_TOK;
    #pragma unroll
    for (int it = 0; it < 8; it++) {
        const int u = it * 256 + tid;
        const int qc = u & 31, d = u >> 5;
        float4 o;
        o.x = SO[(qc * 4 + 0) * 66 + d];
        o.y = SO[(qc * 4 + 1) * 66 + d];
        o.z = SO[(qc * 4 + 2) * 66 + d];
        o.w = SO[(qc * 4 + 3) * 66 + d];
        *(float4*)(pO + (size_t)(h * DHEAD + d) * N_TOK + q0 + qc * 4) = o;
    }
}

// ---------------------------------------------------------------------------
// Split-K combine: g_msg = (pO0 + pO1) / (den0 + den1)
// ---------------------------------------------------------------------------
__global__ void __launch_bounds__(256)
combine_kernel()
{
    const int i   = blockIdx.x * 256 + threadIdx.x;   // [0, 256*1024)
    const int row = i >> 10;          // h*64+d
    const int t4  = (i & 1023) * 4;
    const int hh  = row >> 6;
    const float4 a  = *(const float4*)(g_pO + (size_t)row * N_TOK + t4);
    const float4 b  = *(const float4*)(g_pO + (size_t)DCH * N_TOK + (size_t)row * N_TOK + t4);
    const float4 d0 = *(const float4*)(g_pden + (size_t)hh * N_TOK + t4);
    const float4 d1 = *(const float4*)(g_pden + (size_t)NHEAD * N_TOK + (size_t)hh * N_TOK + t4);
    float4 o;
    o.x = (a.x + b.x) / (d0.x + d1.x);
    o.y = (a.y + b.y) / (d0.y + d1.y);
    o.z = (a.z + b.z) / (d0.z + d1.z);
    o.w = (a.w + b.w) / (d0.w + d1.w);
    *(float4*)(g_msg + (size_t)row * N_TOK + t4) = o;
}

// ---------------------------------------------------------------------------
extern "C" void kernel_launch(void* const* d_in, const int* in_sizes, int n_in,
                              void* d_out, int out_size)
{
    const float* x    = (const float*)d_in[0];
    const float* spat = (const float*)d_in[1];
    const float* Wq   = (const float*)d_in[2];
    const float* bq   = (const float*)d_in[3];
    const float* Wk   = (const float*)d_in[4];
    const float* bk   = (const float*)d_in[5];
    const float* Wv   = (const float*)d_in[6];
    const float* bv   = (const float*)d_in[7];
    const float* W1   = (const float*)d_in[8];
    const float* b1   = (const float*)d_in[9];
    const float* g1   = (const float*)d_in[10];
    const float* be1  = (const float*)d_in[11];
    const float* W2   = (const float*)d_in[12];
    const float* b2   = (const float*)d_in[13];
    const float* g2   = (const float*)d_in[14];
    const float* be2  = (const float*)d_in[15];
    const float* W3   = (const float*)d_in[16];
    const float* b3   = (const float*)d_in[17];
    float* out = (float*)d_out;

    void *pQh, *pKh, *pVh, *pM, *pH1, *pH2;
    cudaGetSymbolAddress(&pQh, g_Qh);
    cudaGetSymbolAddress(&pKh, g_Kh);
    cudaGetSymbolAddress(&pVh, g_Vh);
    cudaGetSymbolAddress(&pM,  g_msg);
    cudaGetSymbolAddress(&pH1, g_h1);
    cudaGetSymbolAddress(&pH2, g_h2);

    const dim3 blk(128);
    gemm_kernel<0><<<dim3(64, 4), blk>>>(Wq, x, pQh, bq, nullptr, nullptr, nullptr, 256);
    gemm_kernel<0><<<dim3(64, 4), blk>>>(Wk, x, pKh, bk, nullptr, nullptr, nullptr, 256);
    gemm_kernel<3><<<dim3(64, 4), blk>>>(Wv, x, pVh, bv, nullptr, nullptr, nullptr, 256);
    attn_kernel<<<dim3(4, 32, KSPLIT), 256>>>(spat);
    combine_kernel<<<1024, 256>>>();
    gemm_kernel<1><<<dim3(64, 2), blk>>>(W1, (const float*)pM,  pH1, b1, g1, be1, nullptr, 256);
    gemm_kernel<1><<<dim3(64, 2), blk>>>(W2, (const float*)pH1, pH2, b2, g2, be2, nullptr, 128);
    gemm_kernel<2><<<dim3(64, 4), blk>>>(W3, (const float*)pH2, out, b3, nullptr, nullptr, x, 128);
}

// round 8
// speedup vs baseline: 6.3213x; 1.0063x over previous
#include <cuda_runtime.h>
#include <cuda_fp16.h>
#include <cstdint>
#include <cstddef>

#define N_TOK 4096
#define DCH   256
#define NHEAD 4
#define DHEAD 64
#define KSPLIT 2

// Scratch (static device arrays — no allocation anywhere)
__device__ __half g_Qh[NHEAD * N_TOK * DHEAD];  // [h][tok][d]
__device__ __half g_Kh[NHEAD * N_TOK * DHEAD];  // [h][tok][d]
__device__ __half g_Vh[DCH * N_TOK];            // [ch][tok]
__device__ float  g_msg[DCH * N_TOK];
__device__ float  g_pO [KSPLIT * DCH * N_TOK];  // split-K partial O, [kt][h*64+d][tok]
__device__ float  g_pden[KSPLIT * NHEAD * N_TOK];
__device__ float  g_h1 [(DCH/2) * N_TOK];
__device__ float  g_h2 [(DCH/2) * N_TOK];

typedef unsigned long long u64;

__device__ __forceinline__ u64 pack2(float lo, float hi) {
    u64 r; asm("mov.b64 %0, {%1,%2};" : "=l"(r) : "f"(lo), "f"(hi)); return r;
}
__device__ __forceinline__ void unpack2(u64 v, float& lo, float& hi) {
    asm("mov.b64 {%0,%1}, %2;" : "=f"(lo), "=f"(hi) : "l"(v));
}
__device__ __forceinline__ void fma2(u64& d, u64 a, u64 b) {
    asm("fma.rn.f32x2 %0, %1, %2, %0;" : "+l"(d) : "l"(a), "l"(b));
}
__device__ __forceinline__ float ex2f(float x) {
    float r; asm("ex2.approx.f32 %0, %1;" : "=f"(r) : "f"(x)); return r;
}
// HMMA m16n8k16 f16 -> f32 accum
__device__ __forceinline__ void hmma(float* c, const uint32_t* a, const uint32_t* b) {
    asm volatile(
        "mma.sync.aligned.m16n8k16.row.col.f32.f16.f16.f32 "
        "{%0,%1,%2,%3}, {%4,%5,%6,%7}, {%8,%9}, {%0,%1,%2,%3};"
        : "+f"(c[0]), "+f"(c[1]), "+f"(c[2]), "+f"(c[3])
        : "r"(a[0]), "r"(a[1]), "r"(a[2]), "r"(a[3]), "r"(b[0]), "r"(b[1]));
}

// ---------------------------------------------------------------------------
// SIMT GEMM with packed f32x2 FMAs (unchanged from passing round).
// ---------------------------------------------------------------------------
template<int EPI>
__global__ void __launch_bounds__(128)
gemm_kernel(const float* __restrict__ A, const float* __restrict__ B,
            void* __restrict__ Cv, const float* __restrict__ bias,
            const float* __restrict__ gamma, const float* __restrict__ beta,
            const float* __restrict__ resid, int K)
{
    __shared__ float As[16][68];
    __shared__ float Bs[16][64];
    const int m0 = blockIdx.y * 64;
    const int n0 = blockIdx.x * 64;
    const int tid = threadIdx.x;
    const int tm = tid >> 4;
    const int tn = tid & 15;

    u64 c2[4][4];
    #pragma unroll
    for (int i = 0; i < 4; i++)
        #pragma unroll
        for (int j = 0; j < 4; j++) c2[i][j] = 0ull;

    const int am = tid >> 2;
    const int ac = (tid & 3) << 2;
    const int br = tid >> 4;
    const int bc = (tid & 15) << 2;

    for (int k0 = 0; k0 < K; k0 += 16) {
        const float4 av0 = *(const float4*)(A + (size_t)(m0 + am     ) * K + k0 + ac);
        const float4 av1 = *(const float4*)(A + (size_t)(m0 + am + 32) * K + k0 + ac);
        const float4 bv0 = *(const float4*)(B + (size_t)(k0 + br    ) * N_TOK + n0 + bc);
        const float4 bv1 = *(const float4*)(B + (size_t)(k0 + br + 8) * N_TOK + n0 + bc);
        __syncthreads();
        As[ac+0][am]    = av0.x; As[ac+1][am]    = av0.y; As[ac+2][am]    = av0.z; As[ac+3][am]    = av0.w;
        As[ac+0][am+32] = av1.x; As[ac+1][am+32] = av1.y; As[ac+2][am+32] = av1.z; As[ac+3][am+32] = av1.w;
        *(float4*)&Bs[br  ][bc] = bv0;
        *(float4*)&Bs[br+8][bc] = bv1;
        __syncthreads();

        #pragma unroll
        for (int k = 0; k < 16; k++) {
            u64 a2[4];
            const float2* arow = (const float2*)&As[k][tm << 3];
            #pragma unroll
            for (int i = 0; i < 4; i++) { float2 t = arow[i]; a2[i] = pack2(t.x, t.y); }
            const float4 bv = *(const float4*)&Bs[k][tn << 2];
            u64 b2[4];
            b2[0] = pack2(bv.x, bv.x); b2[1] = pack2(bv.y, bv.y);
            b2[2] = pack2(bv.z, bv.z); b2[3] = pack2(bv.w, bv.w);
            #pragma unroll
            for (int i = 0; i < 4; i++)
                #pragma unroll
                for (int j = 0; j < 4; j++)
                    fma2(c2[i][j], a2[i], b2[j]);
        }
    }

    #pragma unroll
    for (int i = 0; i < 4; i++) {
        float lo[4], hi[4];
        #pragma unroll
        for (int j = 0; j < 4; j++) unpack2(c2[i][j], lo[j], hi[j]);
        const int mlo = m0 + (tm << 3) + 2 * i;
        const int mhi = mlo + 1;
        const int nc  = n0 + (tn << 2);

        if (EPI == 0) {
            __half* qh = (__half*)Cv;
            const int hh = mlo >> 6, d0 = mlo & 63;
            const float blo = bias[mlo], bhi = bias[mhi];
            #pragma unroll
            for (int j = 0; j < 4; j++) {
                __half2 v = __floats2half2_rn(lo[j] + blo, hi[j] + bhi);
                *(__half2*)(qh + ((size_t)hh * N_TOK + (nc + j)) * DHEAD + d0) = v;
            }
        } else if (EPI == 3) {
            __half* vh = (__half*)Cv;
            const float bl = bias[mlo], bh = bias[mhi];
            __half2 p0 = __floats2half2_rn(lo[0] + bl, lo[1] + bl);
            __half2 p1 = __floats2half2_rn(lo[2] + bl, lo[3] + bl);
            __half2 p2 = __floats2half2_rn(hi[0] + bh, hi[1] + bh);
            __half2 p3 = __floats2half2_rn(hi[2] + bh, hi[3] + bh);
            *(__half2*)(vh + (size_t)mlo * N_TOK + nc)     = p0;
            *(__half2*)(vh + (size_t)mlo * N_TOK + nc + 2) = p1;
            *(__half2*)(vh + (size_t)mhi * N_TOK + nc)     = p2;
            *(__half2*)(vh + (size_t)mhi * N_TOK + nc + 2) = p3;
        } else {
            float* C = (float*)Cv;
            float* rows[2] = { lo, hi };
            int    ms[2]   = { mlo, mhi };
            #pragma unroll
            for (int r = 0; r < 2; r++) {
                float* v = rows[r];
                const int m = ms[r];
                const float b = bias[m];
                float4 o;
                if (EPI == 1) {
                    const float s  = gamma[m] * rsqrtf(1.0f + 1e-5f);
                    const float bb = beta[m];
                    o.x = fmaxf((v[0] + b) * s + bb, 0.0f);
                    o.y = fmaxf((v[1] + b) * s + bb, 0.0f);
                    o.z = fmaxf((v[2] + b) * s + bb, 0.0f);
                    o.w = fmaxf((v[3] + b) * s + bb, 0.0f);
                } else {
                    const float4 rr = *(const float4*)(resid + (size_t)m * N_TOK + nc);
                    o.x = v[0] + b + rr.x; o.y = v[1] + b + rr.y;
                    o.z = v[2] + b + rr.z; o.w = v[3] + b + rr.w;
                }
                *(float4*)(C + (size_t)m * N_TOK + nc) = o;
            }
        }
    }
}

// ---------------------------------------------------------------------------
// Flash attention on HMMA, split-K (2-way), 2 CTAs/SM.
// CTA = (head, 128-query tile, key half). 8 warps x 16 queries, 16 key tiles.
// Fragment staging uses +kc*2 b32 skew -> conflict-free STS; reads stay
// contiguous-256B LDS.64 (8B-aligned). Inner loop chunked per 16 keys so the
// S accumulator is only 8 regs (fits 2 CTAs/SM).  Partials (unnormalized O,
// denom) written to g_pO/g_pden; combine kernel finishes the softmax divide.
// ---------------------------------------------------------------------------
__global__ void __launch_bounds__(256, 2)
attn_kernel(const float* __restrict__ spat)
{
    __shared__ __align__(16) char smbuf[33792];
    uint32_t* KF = (uint32_t*)smbuf;            // skewed frags, 16404B
    uint32_t* VF = (uint32_t*)(smbuf + 16448);  // skewed frags, 16436B
    float*    SO = (float*)smbuf;               // out transpose [128][66]

    const int tid  = threadIdx.x;
    const int w    = tid >> 5;
    const int lane = tid & 31;
    const int h    = blockIdx.x;
    const int q0   = blockIdx.y * 128;
    const int kt   = blockIdx.z;
    const int g    = lane >> 2;
    const int tq   = lane & 3;
    const float SCL = 0.1803368801111204f;   // log2(e)/8

    // ---- persistent Q fragments ----
    uint32_t aq[4][4];
    {
        const __half* qp = g_Qh + ((size_t)h * N_TOK + q0 + w * 16) * DHEAD;
        #pragma unroll
        for (int kc = 0; kc < 4; kc++) {
            const int d0 = kc * 16 + tq * 2;
            aq[kc][0] = *(const uint32_t*)(qp + (size_t)(g    ) * DHEAD + d0);
            aq[kc][1] = *(const uint32_t*)(qp + (size_t)(g + 8) * DHEAD + d0);
            aq[kc][2] = *(const uint32_t*)(qp + (size_t)(g    ) * DHEAD + d0 + 8);
            aq[kc][3] = *(const uint32_t*)(qp + (size_t)(g + 8) * DHEAD + d0 + 8);
        }
    }

    float oacc[8][4];
    #pragma unroll
    for (int i = 0; i < 8; i++)
        #pragma unroll
        for (int j = 0; j < 4; j++) oacc[i][j] = 0.0f;
    float denL = 0.0f, denH = 0.0f;

    const float* spL = spat + (size_t)(q0 + w * 16 + g    ) * N_TOK + tq * 2;
    const float* spH = spat + (size_t)(q0 + w * 16 + g + 8) * N_TOK + tq * 2;

    #pragma unroll 1
    for (int t = 0; t < 32 / KSPLIT; t++) {
        const int kb = (kt * (32 / KSPLIT) + t) * 128;
        __syncthreads();

        // ---- stage K frags (skew kc*2 -> banks = (tok&7)*8 + kc*2 + r, all distinct) ----
        #pragma unroll
        for (int it = 0; it < 4; it++) {
            const int u = it * 256 + tid;
            const int tok = u >> 3, c8 = u & 7;
            const uint4 v = *(const uint4*)(g_Kh + ((size_t)h * N_TOK + kb + tok) * DHEAD + c8 * 8);
            const int kc = c8 >> 1, r = c8 & 1, nt = tok >> 3;
            uint32_t* p = KF + (kc * 16 + nt) * 64 + kc * 2 + (tok & 7) * 8 + r;
            p[0] = v.x; p[2] = v.y; p[4] = v.z; p[6] = v.w;
        }
        // ---- stage V frags (d = tid>>2 spreads rows; banks = (d&7)*8 + kc*2 + r) ----
        #pragma unroll
        for (int it = 0; it < 4; it++) {
            const int d  = tid >> 2;
            const int c8 = it * 4 + (tid & 3);
            const uint4 v = *(const uint4*)(g_Vh + ((size_t)(h * DHEAD + d)) * N_TOK + kb + c8 * 8);
            const int kc = c8 >> 1, r = c8 & 1, nt = d >> 3;
            uint32_t* p = VF + (kc * 8 + nt) * 64 + kc * 2 + (d & 7) * 8 + r;
            p[0] = v.x; p[2] = v.y; p[4] = v.z; p[6] = v.w;
        }
        __syncthreads();

        // ---- 8 chunks of 16 keys: QK -> exp -> PV ----
        #pragma unroll
        for (int c = 0; c < 8; c++) {
            float cS[2][4];
            #pragma unroll
            for (int j = 0; j < 2; j++)
                #pragma unroll
                for (int q = 0; q < 4; q++) cS[j][q] = 0.0f;
            #pragma unroll
            for (int kc = 0; kc < 4; kc++) {
                hmma(cS[0], aq[kc], KF + (kc * 16 + 2 * c    ) * 64 + kc * 2 + lane * 2);
                hmma(cS[1], aq[kc], KF + (kc * 16 + 2 * c + 1) * 64 + kc * 2 + lane * 2);
            }
            uint32_t aP[4];
            #pragma unroll
            for (int j = 0; j < 2; j++) {
                const int nt = 2 * c + j;
                const float2 slo = *(const float2*)(spL + kb + nt * 8);
                const float2 shi = *(const float2*)(spH + kb + nt * 8);
                const float p0 = ex2f(cS[j][0] * slo.x * SCL);
                const float p1 = ex2f(cS[j][1] * slo.y * SCL);
                const float p2 = ex2f(cS[j][2] * shi.x * SCL);
                const float p3 = ex2f(cS[j][3] * shi.y * SCL);
                denL += p0 + p1;
                denH += p2 + p3;
                __half2 h01 = __floats2half2_rn(p0, p1);
                __half2 h23 = __floats2half2_rn(p2, p3);
                aP[j * 2 + 0] = *(uint32_t*)&h01;
                aP[j * 2 + 1] = *(uint32_t*)&h23;
            }
            #pragma unroll
            for (int ntv = 0; ntv < 8; ntv++)
                hmma(oacc[ntv], aP, VF + (c * 8 + ntv) * 64 + c * 2 + lane * 2);
        }
    }

    // quad-reduce denominators
    denL += __shfl_xor_sync(0xFFFFFFFFu, denL, 1);
    denL += __shfl_xor_sync(0xFFFFFFFFu, denL, 2);
    denH += __shfl_xor_sync(0xFFFFFFFFu, denH, 1);
    denH += __shfl_xor_sync(0xFFFFFFFFu, denH, 2);
    if (tq == 0) {
        float* dp = g_pden + (size_t)kt * NHEAD * N_TOK + (size_t)h * N_TOK + q0 + w * 16;
        dp[g]     = denL;
        dp[g + 8] = denH;
    }

    __syncthreads();   // fragment smem -> SO reuse
    {
        const int rowL = w * 16 + g, rowH = rowL + 8;
        #pragma unroll
        for (int nt = 0; nt < 8; nt++) {
            const int col = nt * 8 + tq * 2;
            *(float2*)(SO + rowL * 66 + col) = make_float2(oacc[nt][0], oacc[nt][1]);
            *(float2*)(SO + rowH * 66 + col) = make_float2(oacc[nt][2], oacc[nt][3]);
        }
    }
    __syncthreads();

    // transposed coalesced partial store: g_pO[kt][(h*64+d)][q0..q0+127]
    float* pO = g_pO + (size_t)kt * DCH * N_TOK;
    #pragma unroll
    for (int it = 0; it < 8; it++) {
        const int u = it * 256 + tid;
        const int qc = u & 31, d = u >> 5;
        float4 o;
        o.x = SO[(qc * 4 + 0) * 66 + d];
        o.y = SO[(qc * 4 + 1) * 66 + d];
        o.z = SO[(qc * 4 + 2) * 66 + d];
        o.w = SO[(qc * 4 + 3) * 66 + d];
        *(float4*)(pO + (size_t)(h * DHEAD + d) * N_TOK + q0 + qc * 4) = o;
    }
}

// ---------------------------------------------------------------------------
// Split-K combine: g_msg = (pO0 + pO1) / (den0 + den1)
// ---------------------------------------------------------------------------
__global__ void __launch_bounds__(256)
combine_kernel()
{
    const int i   = blockIdx.x * 256 + threadIdx.x;   // [0, 256*1024)
    const int row = i >> 10;          // h*64+d
    const int t4  = (i & 1023) * 4;
    const int hh  = row >> 6;
    const float4 a  = *(const float4*)(g_pO + (size_t)row * N_TOK + t4);
    const float4 b  = *(const float4*)(g_pO + (size_t)DCH * N_TOK + (size_t)row * N_TOK + t4);
    const float4 d0 = *(const float4*)(g_pden + (size_t)hh * N_TOK + t4);
    const float4 d1 = *(const float4*)(g_pden + (size_t)NHEAD * N_TOK + (size_t)hh * N_TOK + t4);
    float4 o;
    o.x = (a.x + b.x) / (d0.x + d1.x);
    o.y = (a.y + b.y) / (d0.y + d1.y);
    o.z = (a.z + b.z) / (d0.z + d1.z);
    o.w = (a.w + b.w) / (d0.w + d1.w);
    *(float4*)(g_msg + (size_t)row * N_TOK + t4) = o;
}

// ---------------------------------------------------------------------------
extern "C" void kernel_launch(void* const* d_in, const int* in_sizes, int n_in,
                              void* d_out, int out_size)
{
    const float* x    = (const float*)d_in[0];
    const float* spat = (const float*)d_in[1];
    const float* Wq   = (const float*)d_in[2];
    const float* bq   = (const float*)d_in[3];
    const float* Wk   = (const float*)d_in[4];
    const float* bk   = (const float*)d_in[5];
    const float* Wv   = (const float*)d_in[6];
    const float* bv   = (const float*)d_in[7];
    const float* W1   = (const float*)d_in[8];
    const float* b1   = (const float*)d_in[9];
    const float* g1   = (const float*)d_in[10];
    const float* be1  = (const float*)d_in[11];
    const float* W2   = (const float*)d_in[12];
    const float* b2   = (const float*)d_in[13];
    const float* g2   = (const float*)d_in[14];
    const float* be2  = (const float*)d_in[15];
    const float* W3   = (const float*)d_in[16];
    const float* b3   = (const float*)d_in[17];
    float* out = (float*)d_out;

    void *pQh, *pKh, *pVh, *pM, *pH1, *pH2;
    cudaGetSymbolAddress(&pQh, g_Qh);
    cudaGetSymbolAddress(&pKh, g_Kh);
    cudaGetSymbolAddress(&pVh, g_Vh);
    cudaGetSymbolAddress(&pM,  g_msg);
    cudaGetSymbolAddress(&pH1, g_h1);
    cudaGetSymbolAddress(&pH2, g_h2);

    const dim3 blk(128);
    gemm_kernel<0><<<dim3(64, 4), blk>>>(Wq, x, pQh, bq, nullptr, nullptr, nullptr, 256);
    gemm_kernel<0><<<dim3(64, 4), blk>>>(Wk, x, pKh, bk, nullptr, nullptr, nullptr, 256);
    gemm_kernel<3><<<dim3(64, 4), blk>>>(Wv, x, pVh, bv, nullptr, nullptr, nullptr, 256);
    attn_kernel<<<dim3(4, 32, KSPLIT), 256>>>(spat);
    combine_kernel<<<1024, 256>>>();
    gemm_kernel<1><<<dim3(64, 2), blk>>>(W1, (const float*)pM,  pH1, b1, g1, be1, nullptr, 256);
    gemm_kernel<1><<<dim3(64, 2), blk>>>(W2, (const float*)pH1, pH2, b2, g2, be2, nullptr, 128);
    gemm_kernel<2><<<dim3(64, 4), blk>>>(W3, (const float*)pH2, out, b3, nullptr, nullptr, x, 128);
}

// round 9
// speedup vs baseline: 7.6869x; 1.2160x over previous
#include <cuda_runtime.h>
#include <cuda_fp16.h>
#include <cstdint>
#include <cstddef>

#define N_TOK 4096
#define DCH   256
#define NHEAD 4
#define DHEAD 64
#define KSPLIT 2

__device__ __half g_xT  [N_TOK * DCH];           // [tok][ch] f16
__device__ __half g_Wqh [DCH * DCH];
__device__ __half g_Wkh [DCH * DCH];
__device__ __half g_Wvh [DCH * DCH];
__device__ __half g_W1h [(DCH/2) * DCH];
__device__ __half g_W2h [(DCH/2) * (DCH/2)];
__device__ __half g_W3h [DCH * (DCH/2)];
__device__ __half g_Qh  [NHEAD * N_TOK * DHEAD]; // [h][tok][d]
__device__ __half g_Kh  [NHEAD * N_TOK * DHEAD]; // [h][tok][d]
__device__ __half g_Vh  [DCH * N_TOK];           // [ch][tok]
__device__ float  g_pO  [KSPLIT * DCH * N_TOK];
__device__ float  g_pden[KSPLIT * NHEAD * N_TOK];
__device__ __half g_msgT[N_TOK * DCH];           // [tok][ch] f16
__device__ __half g_h1T [N_TOK * (DCH/2)];
__device__ __half g_h2T [N_TOK * (DCH/2)];

__device__ __forceinline__ float ex2f(float x) {
    float r; asm("ex2.approx.f32 %0, %1;" : "=f"(r) : "f"(x)); return r;
}
__device__ __forceinline__ void hmma(float* c, const uint32_t* a, const uint32_t* b) {
    asm volatile(
        "mma.sync.aligned.m16n8k16.row.col.f32.f16.f16.f32 "
        "{%0,%1,%2,%3}, {%4,%5,%6,%7}, {%8,%9}, {%0,%1,%2,%3};"
        : "+f"(c[0]), "+f"(c[1]), "+f"(c[2]), "+f"(c[3])
        : "r"(a[0]), "r"(a[1]), "r"(a[2]), "r"(a[3]), "r"(b[0]), "r"(b[1]));
}

// ---------------- weight f32 -> f16 ----------------
__global__ void __launch_bounds__(256)
wconv_kernel(const float* __restrict__ wq, const float* __restrict__ wk,
             const float* __restrict__ wv, const float* __restrict__ w1,
             const float* __restrict__ w2, const float* __restrict__ w3)
{
    const int i = blockIdx.x * 256 + threadIdx.x;
    if (i < DCH * DCH) {
        g_Wqh[i] = __float2half(wq[i]);
        g_Wkh[i] = __float2half(wk[i]);
        g_Wvh[i] = __float2half(wv[i]);
    }
    if (i < (DCH/2) * DCH) {
        g_W1h[i] = __float2half(w1[i]);
        g_W3h[i] = __float2half(w3[i]);
    }
    if (i < (DCH/2) * (DCH/2)) g_W2h[i] = __float2half(w2[i]);
}

// ---------------- x [ch][tok] f32 -> xT [tok][ch] f16 ----------------
__global__ void __launch_bounds__(256)
xconv_kernel(const float* __restrict__ x)
{
    __shared__ float tile[64 * 65];
    const int tid = threadIdx.x;
    const int tok0 = blockIdx.x * 64, ch0 = blockIdx.y * 64;
    const int ch = tid >> 2;
    #pragma unroll
    for (int it = 0; it < 4; it++) {
        const int col = (tid & 3) * 16 + it * 4;
        const float4 v = *(const float4*)(x + (size_t)(ch0 + ch) * N_TOK + tok0 + col);
        tile[(col+0)*65 + ch] = v.x; tile[(col+1)*65 + ch] = v.y;
        tile[(col+2)*65 + ch] = v.z; tile[(col+3)*65 + ch] = v.w;
    }
    __syncthreads();
    #pragma unroll
    for (int it = 0; it < 2; it++) {
        const int u = it * 256 + tid;
        const int tok = u >> 3, c8 = (u & 7) * 8;
        __half hh[8];
        #pragma unroll
        for (int j = 0; j < 8; j++) hh[j] = __float2half(tile[tok*65 + c8 + j]);
        *(uint4*)(g_xT + (size_t)(tok0 + tok) * DCH + ch0 + c8) = *(uint4*)hh;
    }
}

// ---------------- split-K combine -> msgT [tok][ch] f16 ----------------
__global__ void __launch_bounds__(256)
combine_kernel()
{
    __shared__ float tile[64 * 65];
    const int tid = threadIdx.x;
    const int tok0 = blockIdx.x * 64, h = blockIdx.y, ch0 = h * 64;
    const int ch = tid >> 2;
    #pragma unroll
    for (int it = 0; it < 4; it++) {
        const int col = (tid & 3) * 16 + it * 4;
        const size_t ro = (size_t)(ch0 + ch) * N_TOK + tok0 + col;
        const float4 a  = *(const float4*)(g_pO + ro);
        const float4 b  = *(const float4*)(g_pO + (size_t)DCH * N_TOK + ro);
        const size_t doff = (size_t)h * N_TOK + tok0 + col;
        const float4 d0 = *(const float4*)(g_pden + doff);
        const float4 d1 = *(const float4*)(g_pden + (size_t)NHEAD * N_TOK + doff);
        tile[(col+0)*65 + ch] = (a.x + b.x) / (d0.x + d1.x);
        tile[(col+1)*65 + ch] = (a.y + b.y) / (d0.y + d1.y);
        tile[(col+2)*65 + ch] = (a.z + b.z) / (d0.z + d1.z);
        tile[(col+3)*65 + ch] = (a.w + b.w) / (d0.w + d1.w);
    }
    __syncthreads();
    #pragma unroll
    for (int it = 0; it < 2; it++) {
        const int u = it * 256 + tid;
        const int tok = u >> 3, c8 = (u & 7) * 8;
        __half hh[8];
        #pragma unroll
        for (int j = 0; j < 8; j++) hh[j] = __float2half(tile[tok*65 + c8 + j]);
        *(uint4*)(g_msgT + (size_t)(tok0 + tok) * DCH + ch0 + c8) = *(uint4*)hh;
    }
}

// ---------------------------------------------------------------------------
// HMMA GEMM: C[tok][ch] = A[tok][KD] x W[ch][KD]^T + epilogue.
// CTA 64 tok x 128 ch, 128 thr, warp = 32x64 (2 m-frags x 8 n-frags).
// EPI 0: +bias f16 [h][tok][d] | 1: +bias BN ReLU f16 [tok][M]
// EPI 2: +bias +resid f32 [ch][tok] | 3: +bias f16 [ch][tok]
// ---------------------------------------------------------------------------
template<int KD, int EPI>
__global__ void __launch_bounds__(128, 3)
hgemm_kernel(const __half* __restrict__ A, const __half* __restrict__ W,
             const float* __restrict__ bias,
             const float* __restrict__ gamma, const float* __restrict__ beta,
             const float* __restrict__ resid, void* __restrict__ dst)
{
    __shared__ __align__(16) float smf[64 * 129];
    uint32_t* AF = (uint32_t*)smf;
    const int tid = threadIdx.x;
    const int lane = tid & 31, wid = tid >> 5;
    const int wm = wid & 1, wn = wid >> 1;
    const int g = lane >> 2, tq = lane & 3;
    const int tok0 = blockIdx.x * 64, ch_blk = blockIdx.y * 128;
    constexpr int KC8 = KD / 8;
    constexpr int SH  = (KD == 256) ? 5 : 4;
    constexpr int RW  = KD / 2;

    #pragma unroll
    for (int it = 0; it < (64 * KC8) / 128; it++) {
        const int u = it * 128 + tid;
        const int c8 = u & (KC8 - 1), tok = u >> SH;
        const uint4 v = *(const uint4*)(A + (size_t)(tok0 + tok) * KD + c8 * 8);
        *(uint4*)(AF + tok * RW + (c8 ^ (tok & 7)) * 4) = v;
    }
    __syncthreads();

    float c[2][8][4];
    #pragma unroll
    for (int i = 0; i < 2; i++)
        #pragma unroll
        for (int j = 0; j < 8; j++)
            #pragma unroll
            for (int q = 0; q < 4; q++) c[i][j][q] = 0.0f;

    const __half* Wp = W + (size_t)(ch_blk + wn * 64) * KD;

    #pragma unroll 2
    for (int kc = 0; kc < KD / 16; kc++) {
        uint32_t a[2][4];
        #pragma unroll
        for (int mt = 0; mt < 2; mt++) {
            const int row = wm * 32 + mt * 16 + g;
            const int lo = ((kc * 2    ) ^ g) * 4 + tq;
            const int hi = ((kc * 2 + 1) ^ g) * 4 + tq;
            a[mt][0] = AF[(row    ) * RW + lo];
            a[mt][1] = AF[(row + 8) * RW + lo];
            a[mt][2] = AF[(row    ) * RW + hi];
            a[mt][3] = AF[(row + 8) * RW + hi];
        }
        #pragma unroll
        for (int nt = 0; nt < 8; nt++) {
            const __half* wrow = Wp + (size_t)(nt * 8 + g) * KD + kc * 16 + tq * 2;
            uint32_t b[2];
            b[0] = *(const uint32_t*)(wrow);
            b[1] = *(const uint32_t*)(wrow + 8);
            hmma(c[0][nt], a[0], b);
            hmma(c[1][nt], a[1], b);
        }
    }

    if (EPI == 0) {
        __half* q = (__half*)dst;
        #pragma unroll
        for (int mt = 0; mt < 2; mt++) {
            const int tok = tok0 + wm * 32 + mt * 16 + g;
            #pragma unroll
            for (int nt = 0; nt < 8; nt++) {
                const int ch = ch_blk + wn * 64 + nt * 8 + tq * 2;
                const int hh = ch >> 6, d = ch & 63;
                const float b0 = bias[ch], b1 = bias[ch + 1];
                __half* p = q + ((size_t)hh * N_TOK + tok) * DHEAD + d;
                *(__half2*)p               = __floats2half2_rn(c[mt][nt][0] + b0, c[mt][nt][1] + b1);
                *(__half2*)(p + 8 * DHEAD) = __floats2half2_rn(c[mt][nt][2] + b0, c[mt][nt][3] + b1);
            }
        }
    } else if (EPI == 1) {
        __half* o = (__half*)dst;
        const int M = gridDim.y * 128;
        const float RSQ = rsqrtf(1.0f + 1e-5f);
        #pragma unroll
        for (int mt = 0; mt < 2; mt++) {
            const int tok = tok0 + wm * 32 + mt * 16 + g;
            #pragma unroll
            for (int nt = 0; nt < 8; nt++) {
                const int ch = ch_blk + wn * 64 + nt * 8 + tq * 2;
                const float s0 = gamma[ch] * RSQ, s1 = gamma[ch + 1] * RSQ;
                const float e0 = beta[ch],        e1 = beta[ch + 1];
                const float b0 = bias[ch],        b1 = bias[ch + 1];
                const float v0 = fmaxf((c[mt][nt][0] + b0) * s0 + e0, 0.0f);
                const float v1 = fmaxf((c[mt][nt][1] + b1) * s1 + e1, 0.0f);
                const float v2 = fmaxf((c[mt][nt][2] + b0) * s0 + e0, 0.0f);
                const float v3 = fmaxf((c[mt][nt][3] + b1) * s1 + e1, 0.0f);
                __half* p = o + (size_t)tok * M + ch;
                *(__half2*)p           = __floats2half2_rn(v0, v1);
                *(__half2*)(p + 8 * M) = __floats2half2_rn(v2, v3);
            }
        }
    } else {
        __syncthreads();
        #pragma unroll
        for (int mt = 0; mt < 2; mt++) {
            const int tl = wm * 32 + mt * 16 + g;
            #pragma unroll
            for (int nt = 0; nt < 8; nt++) {
                const int cl = wn * 64 + nt * 8 + tq * 2;
                const float b0 = bias[ch_blk + cl], b1 = bias[ch_blk + cl + 1];
                smf[(tl    ) * 129 + cl    ] = c[mt][nt][0] + b0;
                smf[(tl    ) * 129 + cl + 1] = c[mt][nt][1] + b1;
                smf[(tl + 8) * 129 + cl    ] = c[mt][nt][2] + b0;
                smf[(tl + 8) * 129 + cl + 1] = c[mt][nt][3] + b1;
            }
        }
        __syncthreads();
        if (EPI == 3) {
            __half* o = (__half*)dst;
            #pragma unroll
            for (int it = 0; it < 8; it++) {
                const int u = it * 128 + tid;
                const int ch = u >> 3, t8 = (u & 7) * 8;
                __half hh[8];
                #pragma unroll
                for (int j = 0; j < 8; j++) hh[j] = __float2half(smf[(t8 + j) * 129 + ch]);
                *(uint4*)(o + (size_t)(ch_blk + ch) * N_TOK + tok0 + t8) = *(uint4*)hh;
            }
        } else {
            float* o = (float*)dst;
            #pragma unroll
            for (int it = 0; it < 16; it++) {
                const int u = it * 128 + tid;
                const int ch = u >> 4, t4 = (u & 15) * 4;
                const float4 r = *(const float4*)(resid + (size_t)(ch_blk + ch) * N_TOK + tok0 + t4);
                float4 v;
                v.x = smf[(t4+0)*129 + ch] + r.x;
                v.y = smf[(t4+1)*129 + ch] + r.y;
                v.z = smf[(t4+2)*129 + ch] + r.z;
                v.w = smf[(t4+3)*129 + ch] + r.w;
                *(float4*)(o + (size_t)(ch_blk + ch) * N_TOK + tok0 + t4) = v;
            }
        }
    }
}

// ---------------------------------------------------------------------------
// Flash attention on HMMA, split-K (2-way). Unchanged from R7 (passing).
// ---------------------------------------------------------------------------
__global__ void __launch_bounds__(256, 2)
attn_kernel(const float* __restrict__ spat)
{
    __shared__ __align__(16) char smbuf[33792];
    uint32_t* KF = (uint32_t*)smbuf;
    uint32_t* VF = (uint32_t*)(smbuf + 16448);
    float*    SO = (float*)smbuf;

    const int tid  = threadIdx.x;
    const int w    = tid >> 5;
    const int lane = tid & 31;
    const int h    = blockIdx.x;
    const int q0   = blockIdx.y * 128;
    const int kt   = blockIdx.z;
    const int g    = lane >> 2;
    const int tq   = lane & 3;
    const float SCL = 0.1803368801111204f;   // log2(e)/8

    uint32_t aq[4][4];
    {
        const __half* qp = g_Qh + ((size_t)h * N_TOK + q0 + w * 16) * DHEAD;
        #pragma unroll
        for (int kc = 0; kc < 4; kc++) {
            const int d0 = kc * 16 + tq * 2;
            aq[kc][0] = *(const uint32_t*)(qp + (size_t)(g    ) * DHEAD + d0);
            aq[kc][1] = *(const uint32_t*)(qp + (size_t)(g + 8) * DHEAD + d0);
            aq[kc][2] = *(const uint32_t*)(qp + (size_t)(g    ) * DHEAD + d0 + 8);
            aq[kc][3] = *(const uint32_t*)(qp + (size_t)(g + 8) * DHEAD + d0 + 8);
        }
    }

    float oacc[8][4];
    #pragma unroll
    for (int i = 0; i < 8; i++)
        #pragma unroll
        for (int j = 0; j < 4; j++) oacc[i][j] = 0.0f;
    float denL = 0.0f, denH = 0.0f;

    const float* spL = spat + (size_t)(q0 + w * 16 + g    ) * N_TOK + tq * 2;
    const float* spH = spat + (size_t)(q0 + w * 16 + g + 8) * N_TOK + tq * 2;

    #pragma unroll 1
    for (int t = 0; t < 32 / KSPLIT; t++) {
        const int kb = (kt * (32 / KSPLIT) + t) * 128;
        __syncthreads();

        #pragma unroll
        for (int it = 0; it < 4; it++) {
            const int u = it * 256 + tid;
            const int tok = u >> 3, c8 = u & 7;
            const uint4 v = *(const uint4*)(g_Kh + ((size_t)h * N_TOK + kb + tok) * DHEAD + c8 * 8);
            const int kc = c8 >> 1, r = c8 & 1, nt = tok >> 3;
            uint32_t* p = KF + (kc * 16 + nt) * 64 + kc * 2 + (tok & 7) * 8 + r;
            p[0] = v.x; p[2] = v.y; p[4] = v.z; p[6] = v.w;
        }
        #pragma unroll
        for (int it = 0; it < 4; it++) {
            const int d  = tid >> 2;
            const int c8 = it * 4 + (tid & 3);
            const uint4 v = *(const uint4*)(g_Vh + ((size_t)(h * DHEAD + d)) * N_TOK + kb + c8 * 8);
            const int kc = c8 >> 1, r = c8 & 1, nt = d >> 3;
            uint32_t* p = VF + (kc * 8 + nt) * 64 + kc * 2 + (d & 7) * 8 + r;
            p[0] = v.x; p[2] = v.y; p[4] = v.z; p[6] = v.w;
        }
        __syncthreads();

        #pragma unroll
        for (int c = 0; c < 8; c++) {
            float cS[2][4];
            #pragma unroll
            for (int j = 0; j < 2; j++)
                #pragma unroll
                for (int q = 0; q < 4; q++) cS[j][q] = 0.0f;
            #pragma unroll
            for (int kc = 0; kc < 4; kc++) {
                hmma(cS[0], aq[kc], KF + (kc * 16 + 2 * c    ) * 64 + kc * 2 + lane * 2);
                hmma(cS[1], aq[kc], KF + (kc * 16 + 2 * c + 1) * 64 + kc * 2 + lane * 2);
            }
            uint32_t aP[4];
            #pragma unroll
            for (int j = 0; j < 2; j++) {
                const int nt = 2 * c + j;
                const float2 slo = *(const float2*)(spL + kb + nt * 8);
                const float2 shi = *(const float2*)(spH + kb + nt * 8);
                const float p0 = ex2f(cS[j][0] * slo.x * SCL);
                const float p1 = ex2f(cS[j][1] * slo.y * SCL);
                const float p2 = ex2f(cS[j][2] * shi.x * SCL);
                const float p3 = ex2f(cS[j][3] * shi.y * SCL);
                denL += p0 + p1;
                denH += p2 + p3;
                __half2 h01 = __floats2half2_rn(p0, p1);
                __half2 h23 = __floats2half2_rn(p2, p3);
                aP[j * 2 + 0] = *(uint32_t*)&h01;
                aP[j * 2 + 1] = *(uint32_t*)&h23;
            }
            #pragma unroll
            for (int ntv = 0; ntv < 8; ntv++)
                hmma(oacc[ntv], aP, VF + (c * 8 + ntv) * 64 + c * 2 + lane * 2);
        }
    }

    denL += __shfl_xor_sync(0xFFFFFFFFu, denL, 1);
    denL += __shfl_xor_sync(0xFFFFFFFFu, denL, 2);
    denH += __shfl_xor_sync(0xFFFFFFFFu, denH, 1);
    denH += __shfl_xor_sync(0xFFFFFFFFu, denH, 2);
    if (tq == 0) {
        float* dp = g_pden + (size_t)kt * NHEAD * N_TOK + (size_t)h * N_TOK + q0 + w * 16;
        dp[g]     = denL;
        dp[g + 8] = denH;
    }

    __syncthreads();
    {
        const int rowL = w * 16 + g, rowH = rowL + 8;
        #pragma unroll
        for (int nt = 0; nt < 8; nt++) {
            const int col = nt * 8 + tq * 2;
            *(float2*)(SO + rowL * 66 + col) = make_float2(oacc[nt][0], oacc[nt][1]);
            *(float2*)(SO + rowH * 66 + col) = make_float2(oacc[nt][2], oacc[nt][3]);
        }
    }
    __syncthreads();

    float* pO = g_pO + (size_t)kt * DCH * N_TOK;
    #pragma unroll
    for (int it = 0; it < 8; it++) {
        const int u = it * 256 + tid;
        const int qc = u & 31, d = u >> 5;
        float4 o;
        o.x = SO[(qc * 4 + 0) * 66 + d];
        o.y = SO[(qc * 4 + 1) * 66 + d];
        o.z = SO[(qc * 4 + 2) * 66 + d];
        o.w = SO[(qc * 4 + 3) * 66 + d];
        *(float4*)(pO + (size_t)(h * DHEAD + d) * N_TOK + q0 + qc * 4) = o;
    }
}

// ---------------------------------------------------------------------------
extern "C" void kernel_launch(void* const* d_in, const int* in_sizes, int n_in,
                              void* d_out, int out_size)
{
    const float* x    = (const float*)d_in[0];
    const float* spat = (const float*)d_in[1];
    const float* Wq   = (const float*)d_in[2];
    const float* bq   = (const float*)d_in[3];
    const float* Wk   = (const float*)d_in[4];
    const float* bk   = (const float*)d_in[5];
    const float* Wv   = (const float*)d_in[6];
    const float* bv   = (const float*)d_in[7];
    const float* W1   = (const float*)d_in[8];
    const float* b1   = (const float*)d_in[9];
    const float* g1   = (const float*)d_in[10];
    const float* be1  = (const float*)d_in[11];
    const float* W2   = (const float*)d_in[12];
    const float* b2   = (const float*)d_in[13];
    const float* g2   = (const float*)d_in[14];
    const float* be2  = (const float*)d_in[15];
    const float* W3   = (const float*)d_in[16];
    const float* b3   = (const float*)d_in[17];
    float* out = (float*)d_out;

    void *pxT, *pWq, *pWk, *pWv, *pW1, *pW2, *pW3, *pQh, *pKh, *pVh, *pMT, *pH1, *pH2;
    cudaGetSymbolAddress(&pxT, g_xT);
    cudaGetSymbolAddress(&pWq, g_Wqh);
    cudaGetSymbolAddress(&pWk, g_Wkh);
    cudaGetSymbolAddress(&pWv, g_Wvh);
    cudaGetSymbolAddress(&pW1, g_W1h);
    cudaGetSymbolAddress(&pW2, g_W2h);
    cudaGetSymbolAddress(&pW3, g_W3h);
    cudaGetSymbolAddress(&pQh, g_Qh);
    cudaGetSymbolAddress(&pKh, g_Kh);
    cudaGetSymbolAddress(&pVh, g_Vh);
    cudaGetSymbolAddress(&pMT, g_msgT);
    cudaGetSymbolAddress(&pH1, g_h1T);
    cudaGetSymbolAddress(&pH2, g_h2T);

    wconv_kernel<<<256, 256>>>(Wq, Wk, Wv, W1, W2, W3);
    xconv_kernel<<<dim3(64, 4), 256>>>(x);
    hgemm_kernel<256, 0><<<dim3(64, 2), 128>>>((const __half*)pxT, (const __half*)pWq, bq, nullptr, nullptr, nullptr, pQh);
    hgemm_kernel<256, 0><<<dim3(64, 2), 128>>>((const __half*)pxT, (const __half*)pWk, bk, nullptr, nullptr, nullptr, pKh);
    hgemm_kernel<256, 3><<<dim3(64, 2), 128>>>((const __half*)pxT, (const __half*)pWv, bv, nullptr, nullptr, nullptr, pVh);
    attn_kernel<<<dim3(4, 32, KSPLIT), 256>>>(spat);
    combine_kernel<<<dim3(64, 4), 256>>>();
    hgemm_kernel<256, 1><<<dim3(64, 1), 128>>>((const __half*)pMT, (const __half*)pW1, b1, g1, be1, nullptr, pH1);
    hgemm_kernel<128, 1><<<dim3(64, 1), 128>>>((const __half*)pH1, (const __half*)pW2, b2, g2, be2, nullptr, pH2);
    hgemm_kernel<128, 2><<<dim3(64, 2), 128>>>((const __half*)pH2, (const __half*)pW3, b3, nullptr, nullptr, x, out);
}

// round 11
// speedup vs baseline: 8.3829x; 1.0905x over previous
#include <cuda_runtime.h>
#include <cuda_fp16.h>
#include <cstdint>
#include <cstddef>

#define N_TOK 4096
#define DCH   256
#define NHEAD 4
#define DHEAD 64
#define KSPLIT 2

__device__ __half g_xT  [N_TOK * DCH];           // [tok][ch] f16
__device__ __half g_Wqh [DCH * DCH];
__device__ __half g_Wkh [DCH * DCH];
__device__ __half g_Wvh [DCH * DCH];
__device__ __half g_W1h [(DCH/2) * DCH];
__device__ __half g_W2h [(DCH/2) * (DCH/2)];
__device__ __half g_W3h [DCH * (DCH/2)];
__device__ __half g_Qh  [NHEAD * N_TOK * DHEAD]; // [h][tok][d]
__device__ __half g_Kh  [NHEAD * N_TOK * DHEAD]; // [h][tok][d]
__device__ __half g_Vh  [DCH * N_TOK];           // [ch][tok]
__device__ float  g_pO  [KSPLIT * DCH * N_TOK];
__device__ float  g_pden[KSPLIT * NHEAD * N_TOK];
__device__ __half g_msgT[N_TOK * DCH];
__device__ __half g_h1T [N_TOK * (DCH/2)];
__device__ __half g_h2T [N_TOK * (DCH/2)];

__device__ __forceinline__ float ex2f(float x) {
    float r; asm("ex2.approx.f32 %0, %1;" : "=f"(r) : "f"(x)); return r;
}
__device__ __forceinline__ void hmma(float* c, const uint32_t* a, const uint32_t* b) {
    asm volatile(
        "mma.sync.aligned.m16n8k16.row.col.f32.f16.f16.f32 "
        "{%0,%1,%2,%3}, {%4,%5,%6,%7}, {%8,%9}, {%0,%1,%2,%3};"
        : "+f"(c[0]), "+f"(c[1]), "+f"(c[2]), "+f"(c[3])
        : "r"(a[0]), "r"(a[1]), "r"(a[2]), "r"(a[3]), "r"(b[0]), "r"(b[1]));
}

// ---------------- weight f32 -> f16 ----------------
__global__ void __launch_bounds__(256)
wconv_kernel(const float* __restrict__ wq, const float* __restrict__ wk,
             const float* __restrict__ wv, const float* __restrict__ w1,
             const float* __restrict__ w2, const float* __restrict__ w3)
{
    const int i = blockIdx.x * 256 + threadIdx.x;
    if (i < DCH * DCH) {
        g_Wqh[i] = __float2half(wq[i]);
        g_Wkh[i] = __float2half(wk[i]);
        g_Wvh[i] = __float2half(wv[i]);
    }
    if (i < (DCH/2) * DCH) {
        g_W1h[i] = __float2half(w1[i]);
        g_W3h[i] = __float2half(w3[i]);
    }
    if (i < (DCH/2) * (DCH/2)) g_W2h[i] = __float2half(w2[i]);
}

// ---------------- x [ch][tok] f32 -> xT [tok][ch] f16 ----------------
__global__ void __launch_bounds__(256)
xconv_kernel(const float* __restrict__ x)
{
    __shared__ float tile[64 * 65];
    const int tid = threadIdx.x;
    const int tok0 = blockIdx.x * 64, ch0 = blockIdx.y * 64;
    const int ch = tid >> 2;
    #pragma unroll
    for (int it = 0; it < 4; it++) {
        const int col = (tid & 3) * 16 + it * 4;
        const float4 v = *(const float4*)(x + (size_t)(ch0 + ch) * N_TOK + tok0 + col);
        tile[(col+0)*65 + ch] = v.x; tile[(col+1)*65 + ch] = v.y;
        tile[(col+2)*65 + ch] = v.z; tile[(col+3)*65 + ch] = v.w;
    }
    __syncthreads();
    #pragma unroll
    for (int it = 0; it < 2; it++) {
        const int u = it * 256 + tid;
        const int tok = u >> 3, c8 = (u & 7) * 8;
        __half hh[8];
        #pragma unroll
        for (int j = 0; j < 8; j++) hh[j] = __float2half(tile[tok*65 + c8 + j]);
        *(uint4*)(g_xT + (size_t)(tok0 + tok) * DCH + ch0 + c8) = *(uint4*)hh;
    }
}

// ---------------- split-K combine -> msgT [tok][ch] f16 ----------------
__global__ void __launch_bounds__(256)
combine_kernel()
{
    __shared__ float tile[64 * 65];
    const int tid = threadIdx.x;
    const int tok0 = blockIdx.x * 64, h = blockIdx.y, ch0 = h * 64;
    const int ch = tid >> 2;
    #pragma unroll
    for (int it = 0; it < 4; it++) {
        const int col = (tid & 3) * 16 + it * 4;
        const size_t ro = (size_t)(ch0 + ch) * N_TOK + tok0 + col;
        const float4 a  = *(const float4*)(g_pO + ro);
        const float4 b  = *(const float4*)(g_pO + (size_t)DCH * N_TOK + ro);
        const size_t doff = (size_t)h * N_TOK + tok0 + col;
        const float4 d0 = *(const float4*)(g_pden + doff);
        const float4 d1 = *(const float4*)(g_pden + (size_t)NHEAD * N_TOK + doff);
        tile[(col+0)*65 + ch] = (a.x + b.x) / (d0.x + d1.x);
        tile[(col+1)*65 + ch] = (a.y + b.y) / (d0.y + d1.y);
        tile[(col+2)*65 + ch] = (a.z + b.z) / (d0.z + d1.z);
        tile[(col+3)*65 + ch] = (a.w + b.w) / (d0.w + d1.w);
    }
    __syncthreads();
    #pragma unroll
    for (int it = 0; it < 2; it++) {
        const int u = it * 256 + tid;
        const int tok = u >> 3, c8 = (u & 7) * 8;
        __half hh[8];
        #pragma unroll
        for (int j = 0; j < 8; j++) hh[j] = __float2half(tile[tok*65 + c8 + j]);
        *(uint4*)(g_msgT + (size_t)(tok0 + tok) * DCH + ch0 + c8) = *(uint4*)hh;
    }
}

// ---------------------------------------------------------------------------
// HMMA GEMM template (MLP + output; unchanged from R9 passing kernel).
// ---------------------------------------------------------------------------
template<int KD, int EPI>
__global__ void __launch_bounds__(128, 3)
hgemm_kernel(const __half* __restrict__ A, const __half* __restrict__ W,
             const float* __restrict__ bias,
             const float* __restrict__ gamma, const float* __restrict__ beta,
             const float* __restrict__ resid, void* __restrict__ dst)
{
    __shared__ __align__(16) float smf[64 * 129];
    uint32_t* AF = (uint32_t*)smf;
    const int tid = threadIdx.x;
    const int lane = tid & 31, wid = tid >> 5;
    const int wm = wid & 1, wn = wid >> 1;
    const int g = lane >> 2, tq = lane & 3;
    const int tok0 = blockIdx.x * 64, ch_blk = blockIdx.y * 128;
    constexpr int KC8 = KD / 8;
    constexpr int SH  = (KD == 256) ? 5 : 4;
    constexpr int RW  = KD / 2;

    #pragma unroll
    for (int it = 0; it < (64 * KC8) / 128; it++) {
        const int u = it * 128 + tid;
        const int c8 = u & (KC8 - 1), tok = u >> SH;
        const uint4 v = *(const uint4*)(A + (size_t)(tok0 + tok) * KD + c8 * 8);
        *(uint4*)(AF + tok * RW + (c8 ^ (tok & 7)) * 4) = v;
    }
    __syncthreads();

    float c[2][8][4];
    #pragma unroll
    for (int i = 0; i < 2; i++)
        #pragma unroll
        for (int j = 0; j < 8; j++)
            #pragma unroll
            for (int q = 0; q < 4; q++) c[i][j][q] = 0.0f;

    const __half* Wp = W + (size_t)(ch_blk + wn * 64) * KD;

    #pragma unroll 2
    for (int kc = 0; kc < KD / 16; kc++) {
        uint32_t a[2][4];
        #pragma unroll
        for (int mt = 0; mt < 2; mt++) {
            const int row = wm * 32 + mt * 16 + g;
            const int lo = ((kc * 2    ) ^ g) * 4 + tq;
            const int hi = ((kc * 2 + 1) ^ g) * 4 + tq;
            a[mt][0] = AF[(row    ) * RW + lo];
            a[mt][1] = AF[(row + 8) * RW + lo];
            a[mt][2] = AF[(row    ) * RW + hi];
            a[mt][3] = AF[(row + 8) * RW + hi];
        }
        #pragma unroll
        for (int nt = 0; nt < 8; nt++) {
            const __half* wrow = Wp + (size_t)(nt * 8 + g) * KD + kc * 16 + tq * 2;
            uint32_t b[2];
            b[0] = *(const uint32_t*)(wrow);
            b[1] = *(const uint32_t*)(wrow + 8);
            hmma(c[0][nt], a[0], b);
            hmma(c[1][nt], a[1], b);
        }
    }

    if (EPI == 1) {
        __half* o = (__half*)dst;
        const int M = gridDim.y * 128;
        const float RSQ = rsqrtf(1.0f + 1e-5f);
        #pragma unroll
        for (int mt = 0; mt < 2; mt++) {
            const int tok = tok0 + wm * 32 + mt * 16 + g;
            #pragma unroll
            for (int nt = 0; nt < 8; nt++) {
                const int ch = ch_blk + wn * 64 + nt * 8 + tq * 2;
                const float s0 = gamma[ch] * RSQ, s1 = gamma[ch + 1] * RSQ;
                const float e0 = beta[ch],        e1 = beta[ch + 1];
                const float b0 = bias[ch],        b1 = bias[ch + 1];
                const float v0 = fmaxf((c[mt][nt][0] + b0) * s0 + e0, 0.0f);
                const float v1 = fmaxf((c[mt][nt][1] + b1) * s1 + e1, 0.0f);
                const float v2 = fmaxf((c[mt][nt][2] + b0) * s0 + e0, 0.0f);
                const float v3 = fmaxf((c[mt][nt][3] + b1) * s1 + e1, 0.0f);
                __half* p = o + (size_t)tok * M + ch;
                *(__half2*)p           = __floats2half2_rn(v0, v1);
                *(__half2*)(p + 8 * M) = __floats2half2_rn(v2, v3);
            }
        }
    } else {
        __syncthreads();
        #pragma unroll
        for (int mt = 0; mt < 2; mt++) {
            const int tl = wm * 32 + mt * 16 + g;
            #pragma unroll
            for (int nt = 0; nt < 8; nt++) {
                const int cl = wn * 64 + nt * 8 + tq * 2;
                const float b0 = bias[ch_blk + cl], b1 = bias[ch_blk + cl + 1];
                smf[(tl    ) * 129 + cl    ] = c[mt][nt][0] + b0;
                smf[(tl    ) * 129 + cl + 1] = c[mt][nt][1] + b1;
                smf[(tl + 8) * 129 + cl    ] = c[mt][nt][2] + b0;
                smf[(tl + 8) * 129 + cl + 1] = c[mt][nt][3] + b1;
            }
        }
        __syncthreads();
        float* o = (float*)dst;
        #pragma unroll
        for (int it = 0; it < 16; it++) {
            const int u = it * 128 + tid;
            const int ch = u >> 4, t4 = (u & 15) * 4;
            const float4 r = *(const float4*)(resid + (size_t)(ch_blk + ch) * N_TOK + tok0 + t4);
            float4 v;
            v.x = smf[(t4+0)*129 + ch] + r.x;
            v.y = smf[(t4+1)*129 + ch] + r.y;
            v.z = smf[(t4+2)*129 + ch] + r.z;
            v.w = smf[(t4+3)*129 + ch] + r.w;
            *(float4*)(o + (size_t)(ch_blk + ch) * N_TOK + tok0 + t4) = v;
        }
    }
}

// ---------------------------------------------------------------------------
// Fused QKV GEMM: grid (64 tok-tiles, 6). blockIdx.y: 0,1=Q 2,3=K 4,5=V.
// Body identical to hgemm_kernel<256,·>; epilogue: Q/K f16 [h][tok][d],
// V f16 [ch][tok] via smem transpose.
// ---------------------------------------------------------------------------
__global__ void __launch_bounds__(128, 3)
hgemm_qkv(const __half* __restrict__ A,
          const __half* __restrict__ Wq, const __half* __restrict__ Wk,
          const __half* __restrict__ Wv,
          const float* __restrict__ bq, const float* __restrict__ bk,
          const float* __restrict__ bv)
{
    constexpr int KD = 256, KC8 = 32, SH = 5, RW = 128;
    __shared__ __align__(16) float smf[64 * 129];
    uint32_t* AF = (uint32_t*)smf;
    const int tid = threadIdx.x;
    const int lane = tid & 31, wid = tid >> 5;
    const int wm = wid & 1, wn = wid >> 1;
    const int g = lane >> 2, tq = lane & 3;
    const int tok0 = blockIdx.x * 64;
    const int s = blockIdx.y, which = s >> 1, ch_blk = (s & 1) * 128;
    const __half* W = (which == 0) ? Wq : (which == 1) ? Wk : Wv;
    const float* bias = (which == 0) ? bq : (which == 1) ? bk : bv;

    #pragma unroll
    for (int it = 0; it < (64 * KC8) / 128; it++) {
        const int u = it * 128 + tid;
        const int c8 = u & (KC8 - 1), tok = u >> SH;
        const uint4 v = *(const uint4*)(A + (size_t)(tok0 + tok) * KD + c8 * 8);
        *(uint4*)(AF + tok * RW + (c8 ^ (tok & 7)) * 4) = v;
    }
    __syncthreads();

    float c[2][8][4];
    #pragma unroll
    for (int i = 0; i < 2; i++)
        #pragma unroll
        for (int j = 0; j < 8; j++)
            #pragma unroll
            for (int q = 0; q < 4; q++) c[i][j][q] = 0.0f;

    const __half* Wp = W + (size_t)(ch_blk + wn * 64) * KD;

    #pragma unroll 2
    for (int kc = 0; kc < KD / 16; kc++) {
        uint32_t a[2][4];
        #pragma unroll
        for (int mt = 0; mt < 2; mt++) {
            const int row = wm * 32 + mt * 16 + g;
            const int lo = ((kc * 2    ) ^ g) * 4 + tq;
            const int hi = ((kc * 2 + 1) ^ g) * 4 + tq;
            a[mt][0] = AF[(row    ) * RW + lo];
            a[mt][1] = AF[(row + 8) * RW + lo];
            a[mt][2] = AF[(row    ) * RW + hi];
            a[mt][3] = AF[(row + 8) * RW + hi];
        }
        #pragma unroll
        for (int nt = 0; nt < 8; nt++) {
            const __half* wrow = Wp + (size_t)(nt * 8 + g) * KD + kc * 16 + tq * 2;
            uint32_t b[2];
            b[0] = *(const uint32_t*)(wrow);
            b[1] = *(const uint32_t*)(wrow + 8);
            hmma(c[0][nt], a[0], b);
            hmma(c[1][nt], a[1], b);
        }
    }

    if (which < 2) {
        __half* q = (which == 0) ? g_Qh : g_Kh;
        #pragma unroll
        for (int mt = 0; mt < 2; mt++) {
            const int tok = tok0 + wm * 32 + mt * 16 + g;
            #pragma unroll
            for (int nt = 0; nt < 8; nt++) {
                const int ch = ch_blk + wn * 64 + nt * 8 + tq * 2;
                const int hh = ch >> 6, d = ch & 63;
                const float b0 = bias[ch], b1 = bias[ch + 1];
                __half* p = q + ((size_t)hh * N_TOK + tok) * DHEAD + d;
                *(__half2*)p               = __floats2half2_rn(c[mt][nt][0] + b0, c[mt][nt][1] + b1);
                *(__half2*)(p + 8 * DHEAD) = __floats2half2_rn(c[mt][nt][2] + b0, c[mt][nt][3] + b1);
            }
        }
    } else {
        __syncthreads();
        #pragma unroll
        for (int mt = 0; mt < 2; mt++) {
            const int tl = wm * 32 + mt * 16 + g;
            #pragma unroll
            for (int nt = 0; nt < 8; nt++) {
                const int cl = wn * 64 + nt * 8 + tq * 2;
                const float b0 = bias[ch_blk + cl], b1 = bias[ch_blk + cl + 1];
                smf[(tl    ) * 129 + cl    ] = c[mt][nt][0] + b0;
                smf[(tl    ) * 129 + cl + 1] = c[mt][nt][1] + b1;
                smf[(tl + 8) * 129 + cl    ] = c[mt][nt][2] + b0;
                smf[(tl + 8) * 129 + cl + 1] = c[mt][nt][3] + b1;
            }
        }
        __syncthreads();
        #pragma unroll
        for (int it = 0; it < 8; it++) {
            const int u = it * 128 + tid;
            const int ch = u >> 3, t8 = (u & 7) * 8;
            __half hh[8];
            #pragma unroll
            for (int j = 0; j < 8; j++) hh[j] = __float2half(smf[(t8 + j) * 129 + ch]);
            *(uint4*)(g_Vh + (size_t)(ch_blk + ch) * N_TOK + tok0 + t8) = *(uint4*)hh;
        }
    }
}

// ---------------------------------------------------------------------------
// Flash attention, warp-m=32: warp owns 32 queries (2 m-frags), so each K/V
// B-fragment LDS feeds 2 HMMAs (crossbar bytes per query halved vs R7).
// CTA = 256 thr / 8 warps / 256 queries; grid (4 heads, 16 qtiles, 2 ksplit).
// Staging + fragment layouts identical to R7 (proven). Output in two
// 128-query passes through the same smem transpose buffer.
// ---------------------------------------------------------------------------
__global__ void __launch_bounds__(256, 1)
attn_kernel(const float* __restrict__ spat)
{
    __shared__ __align__(16) char smbuf[33792];
    uint32_t* KF = (uint32_t*)smbuf;
    uint32_t* VF = (uint32_t*)(smbuf + 16448);
    float*    SO = (float*)smbuf;

    const int tid  = threadIdx.x;
    const int w    = tid >> 5;
    const int lane = tid & 31;
    const int h    = blockIdx.x;
    const int q0   = blockIdx.y * 256;
    const int kt   = blockIdx.z;
    const int g    = lane >> 2;
    const int tq   = lane & 3;
    const float SCL = 0.1803368801111204f;   // log2(e)/8

    uint32_t aq[2][4][4];
    #pragma unroll
    for (int mt = 0; mt < 2; mt++) {
        const __half* qp = g_Qh + ((size_t)h * N_TOK + q0 + w * 32 + mt * 16) * DHEAD;
        #pragma unroll
        for (int kc = 0; kc < 4; kc++) {
            const int d0 = kc * 16 + tq * 2;
            aq[mt][kc][0] = *(const uint32_t*)(qp + (size_t)(g    ) * DHEAD + d0);
            aq[mt][kc][1] = *(const uint32_t*)(qp + (size_t)(g + 8) * DHEAD + d0);
            aq[mt][kc][2] = *(const uint32_t*)(qp + (size_t)(g    ) * DHEAD + d0 + 8);
            aq[mt][kc][3] = *(const uint32_t*)(qp + (size_t)(g + 8) * DHEAD + d0 + 8);
        }
    }

    float oacc[2][8][4];
    #pragma unroll
    for (int m = 0; m < 2; m++)
        #pragma unroll
        for (int i = 0; i < 8; i++)
            #pragma unroll
            for (int j = 0; j < 4; j++) oacc[m][i][j] = 0.0f;
    float den[2][2] = {{0.0f, 0.0f}, {0.0f, 0.0f}};

    const float* sp[2][2];
    #pragma unroll
    for (int mt = 0; mt < 2; mt++) {
        sp[mt][0] = spat + (size_t)(q0 + w * 32 + mt * 16 + g    ) * N_TOK + tq * 2;
        sp[mt][1] = spat + (size_t)(q0 + w * 32 + mt * 16 + g + 8) * N_TOK + tq * 2;
    }

    #pragma unroll 1
    for (int t = 0; t < 32 / KSPLIT; t++) {
        const int kb = (kt * (32 / KSPLIT) + t) * 128;
        __syncthreads();

        #pragma unroll
        for (int it = 0; it < 4; it++) {
            const int u = it * 256 + tid;
            const int tok = u >> 3, c8 = u & 7;
            const uint4 v = *(const uint4*)(g_Kh + ((size_t)h * N_TOK + kb + tok) * DHEAD + c8 * 8);
            const int kc = c8 >> 1, r = c8 & 1, nt = tok >> 3;
            uint32_t* p = KF + (kc * 16 + nt) * 64 + kc * 2 + (tok & 7) * 8 + r;
            p[0] = v.x; p[2] = v.y; p[4] = v.z; p[6] = v.w;
        }
        #pragma unroll
        for (int it = 0; it < 4; it++) {
            const int d  = tid >> 2;
            const int c8 = it * 4 + (tid & 3);
            const uint4 v = *(const uint4*)(g_Vh + ((size_t)(h * DHEAD + d)) * N_TOK + kb + c8 * 8);
            const int kc = c8 >> 1, r = c8 & 1, nt = d >> 3;
            uint32_t* p = VF + (kc * 8 + nt) * 64 + kc * 2 + (d & 7) * 8 + r;
            p[0] = v.x; p[2] = v.y; p[4] = v.z; p[6] = v.w;
        }
        __syncthreads();

        #pragma unroll
        for (int c = 0; c < 8; c++) {
            float cS[2][2][4];
            #pragma unroll
            for (int m = 0; m < 2; m++)
                #pragma unroll
                for (int j = 0; j < 2; j++)
                    #pragma unroll
                    for (int q = 0; q < 4; q++) cS[m][j][q] = 0.0f;
            #pragma unroll
            for (int kc = 0; kc < 4; kc++) {
                const uint32_t* b0 = KF + (kc * 16 + 2 * c    ) * 64 + kc * 2 + lane * 2;
                const uint32_t* b1 = KF + (kc * 16 + 2 * c + 1) * 64 + kc * 2 + lane * 2;
                hmma(cS[0][0], aq[0][kc], b0);
                hmma(cS[1][0], aq[1][kc], b0);
                hmma(cS[0][1], aq[0][kc], b1);
                hmma(cS[1][1], aq[1][kc], b1);
            }
            uint32_t aP[2][4];
            #pragma unroll
            for (int mt = 0; mt < 2; mt++)
                #pragma unroll
                for (int j = 0; j < 2; j++) {
                    const int nt = 2 * c + j;
                    const float2 slo = *(const float2*)(sp[mt][0] + kb + nt * 8);
                    const float2 shi = *(const float2*)(sp[mt][1] + kb + nt * 8);
                    const float p0 = ex2f(cS[mt][j][0] * slo.x * SCL);
                    const float p1 = ex2f(cS[mt][j][1] * slo.y * SCL);
                    const float p2 = ex2f(cS[mt][j][2] * shi.x * SCL);
                    const float p3 = ex2f(cS[mt][j][3] * shi.y * SCL);
                    den[mt][0] += p0 + p1;
                    den[mt][1] += p2 + p3;
                    __half2 h01 = __floats2half2_rn(p0, p1);
                    __half2 h23 = __floats2half2_rn(p2, p3);
                    aP[mt][j * 2 + 0] = *(uint32_t*)&h01;
                    aP[mt][j * 2 + 1] = *(uint32_t*)&h23;
                }
            #pragma unroll
            for (int ntv = 0; ntv < 8; ntv++) {
                const uint32_t* vb = VF + (c * 8 + ntv) * 64 + c * 2 + lane * 2;
                hmma(oacc[0][ntv], aP[0], vb);
                hmma(oacc[1][ntv], aP[1], vb);
            }
        }
    }

    #pragma unroll
    for (int mt = 0; mt < 2; mt++) {
        den[mt][0] += __shfl_xor_sync(0xFFFFFFFFu, den[mt][0], 1);
        den[mt][0] += __shfl_xor_sync(0xFFFFFFFFu, den[mt][0], 2);
        den[mt][1] += __shfl_xor_sync(0xFFFFFFFFu, den[mt][1], 1);
        den[mt][1] += __shfl_xor_sync(0xFFFFFFFFu, den[mt][1], 2);
    }
    if (tq == 0) {
        float* dp = g_pden + (size_t)kt * NHEAD * N_TOK + (size_t)h * N_TOK + q0 + w * 32;
        dp[g]          = den[0][0];
        dp[g + 8]      = den[0][1];
        dp[16 + g]     = den[1][0];
        dp[16 + g + 8] = den[1][1];
    }

    float* pO = g_pO + (size_t)kt * DCH * N_TOK;
    #pragma unroll
    for (int rep = 0; rep < 2; rep++) {
        __syncthreads();
        if ((w >> 2) == rep) {
            const int wl = w & 3;
            #pragma unroll
            for (int mt = 0; mt < 2; mt++) {
                const int rowL = wl * 32 + mt * 16 + g, rowH = rowL + 8;
                #pragma unroll
                for (int nt = 0; nt < 8; nt++) {
                    const int col = nt * 8 + tq * 2;
                    *(float2*)(SO + rowL * 66 + col) = make_float2(oacc[mt][nt][0], oacc[mt][nt][1]);
                    *(float2*)(SO + rowH * 66 + col) = make_float2(oacc[mt][nt][2], oacc[mt][nt][3]);
                }
            }
        }
        __syncthreads();
        const int qb = q0 + rep * 128;
        #pragma unroll
        for (int it = 0; it < 8; it++) {
            const int u = it * 256 + tid;
            const int qc = u & 31, d = u >> 5;
            float4 o;
            o.x = SO[(qc * 4 + 0) * 66 + d];
            o.y = SO[(qc * 4 + 1) * 66 + d];
            o.z = SO[(qc * 4 + 2) * 66 + d];
            o.w = SO[(qc * 4 + 3) * 66 + d];
            *(float4*)(pO + (size_t)(h * DHEAD + d) * N_TOK + qb + qc * 4) = o;
        }
    }
}

// ---------------------------------------------------------------------------
extern "C" void kernel_launch(void* const* d_in, const int* in_sizes, int n_in,
                              void* d_out, int out_size)
{
    const float* x    = (const float*)d_in[0];
    const float* spat = (const float*)d_in[1];
    const float* Wq   = (const float*)d_in[2];
    const float* bq   = (const float*)d_in[3];
    const float* Wk   = (const float*)d_in[4];
    const float* bk   = (const float*)d_in[5];
    const float* Wv   = (const float*)d_in[6];
    const float* bv   = (const float*)d_in[7];
    const float* W1   = (const float*)d_in[8];
    const float* b1   = (const float*)d_in[9];
    const float* g1   = (const float*)d_in[10];
    const float* be1  = (const float*)d_in[11];
    const float* W2   = (const float*)d_in[12];
    const float* b2   = (const float*)d_in[13];
    const float* g2   = (const float*)d_in[14];
    const float* be2  = (const float*)d_in[15];
    const float* W3   = (const float*)d_in[16];
    const float* b3   = (const float*)d_in[17];
    float* out = (float*)d_out;

    void *pxT, *pWq, *pWk, *pWv, *pW1, *pW2, *pW3, *pMT, *pH1, *pH2;
    cudaGetSymbolAddress(&pxT, g_xT);
    cudaGetSymbolAddress(&pWq, g_Wqh);
    cudaGetSymbolAddress(&pWk, g_Wkh);
    cudaGetSymbolAddress(&pWv, g_Wvh);
    cudaGetSymbolAddress(&pW1, g_W1h);
    cudaGetSymbolAddress(&pW2, g_W2h);
    cudaGetSymbolAddress(&pW3, g_W3h);
    cudaGetSymbolAddress(&pMT, g_msgT);
    cudaGetSymbolAddress(&pH1, g_h1T);
    cudaGetSymbolAddress(&pH2, g_h2T);

    wconv_kernel<<<256, 256>>>(Wq, Wk, Wv, W1, W2, W3);
    xconv_kernel<<<dim3(64, 4), 256>>>(x);
    hgemm_qkv<<<dim3(64, 6), 128>>>((const __half*)pxT,
        (const __half*)pWq, (const __half*)pWk, (const __half*)pWv, bq, bk, bv);
    attn_kernel<<<dim3(4, 16, KSPLIT), 256>>>(spat);
    combine_kernel<<<dim3(64, 4), 256>>>();
    hgemm_kernel<256, 1><<<dim3(64, 1), 128>>>((const __half*)pMT, (const __half*)pW1, b1, g1, be1, nullptr, pH1);
    hgemm_kernel<128, 1><<<dim3(64, 1), 128>>>((const __half*)pH1, (const __half*)pW2, b2, g2, be2, nullptr, pH2);
    hgemm_kernel<128, 2><<<dim3(64, 2), 128>>>((const __half*)pH2, (const __half*)pW3, b3, nullptr, nullptr, x, out);
}